// round 11
// baseline (speedup 1.0000x reference)
#include <cuda_runtime.h>
#include <math.h>

#define NN 50000
#define HD 128
#define OD 256
#define NE 800000
#define LN_EPS 1e-5f

typedef unsigned long long u64;

// ---------------- scratch (static device globals; no allocation) ----------------
__device__ float g_hA[NN * HD];
__device__ float g_hB[NN * HD];
__device__ float g_f [NN * HD];
__device__ float g_yA [NN * OD];
__device__ int   g_off [4][NN + 1];
__device__ int   g_ssrc[4][NE];
__device__ int   g_cnt[4][NN];
__device__ int   g_cur[4][NN];
__device__ int   g_flagIsInt;

// ---------------- helpers ----------------
__device__ __forceinline__ u64 pack2(float lo, float hi) {
    u64 r;
    asm("mov.b64 %0, {%1, %2};" : "=l"(r) : "f"(lo), "f"(hi));
    return r;
}
__device__ __forceinline__ void unpack2(u64 v, float& lo, float& hi) {
    asm("mov.b64 {%0, %1}, %2;" : "=f"(lo), "=f"(hi) : "l"(v));
}
__device__ __forceinline__ u64 fma2(u64 a, u64 b, u64 c) {
    u64 d;
    asm("fma.rn.f32x2 %0, %1, %2, %3;" : "=l"(d) : "l"(a), "l"(b), "l"(c));
    return d;
}
__device__ __forceinline__ u64 mul2(u64 a, u64 b) {
    u64 d;
    asm("mul.rn.f32x2 %0, %1, %2;" : "=l"(d) : "l"(a), "l"(b));
    return d;
}
__device__ __forceinline__ u64 add2(u64 a, u64 b) {
    u64 d;
    asm("add.rn.f32x2 %0, %1, %2;" : "=l"(d) : "l"(a), "l"(b));
    return d;
}
__device__ __forceinline__ u64 abs2(u64 a) {
    return a & 0x7FFFFFFF7FFFFFFFULL;
}

// ---------------- kernels ----------------

// Detect flag buffer layout: int32 (bytes 1..3 of each word are 0) vs uint8.
__global__ void k_detect_flag(const unsigned char* __restrict__ flag) {
    __shared__ int cnt;
    if (threadIdx.x == 0) cnt = 0;
    __syncthreads();
    int local = 0;
    for (int i = threadIdx.x; i < 4000; i += 256)
        if ((i & 3) != 0 && flag[i] != 0) local = 1;
    if (local) atomicOr(&cnt, 1);
    __syncthreads();
    if (threadIdx.x == 0) g_flagIsInt = (cnt == 0) ? 1 : 0;
}

// -------- counting sort by dst (all 4 relations in one grid via blockIdx.y) --------
__global__ void k_hist4(const int* __restrict__ d0, const int* __restrict__ d1,
                        const int* __restrict__ d2, const int* __restrict__ d3,
                        int* __restrict__ cnt) {
    int e = blockIdx.x * 256 + threadIdx.x;
    int r = blockIdx.y;
    const int* dst = r == 0 ? d0 : r == 1 ? d1 : r == 2 ? d2 : d3;
    if (e < NE) atomicAdd(&cnt[r * NN + dst[e]], 1);
}

// 4 blocks, one relation each: exclusive scan -> offs[NN+1], cur[NN]
__global__ void k_scan4(const int* __restrict__ cntAll, int* __restrict__ offsAll,
                        int* __restrict__ curAll) {
    __shared__ int part[1024];
    const int CH = (NN + 1023) / 1024;
    int r = blockIdx.x;
    const int* cnt = cntAll + r * NN;
    int* offs = offsAll + r * (NN + 1);
    int* cur  = curAll  + r * NN;
    int t = threadIdx.x;
    int lo = t * CH, hi = min(lo + CH, NN);
    int s = 0;
    for (int i = lo; i < hi; ++i) s += cnt[i];
    part[t] = s;
    __syncthreads();
    for (int o = 1; o < 1024; o <<= 1) {
        int v = (t >= o) ? part[t - o] : 0;
        __syncthreads();
        part[t] += v;
        __syncthreads();
    }
    int base = (t == 0) ? 0 : part[t - 1];
    for (int i = lo; i < hi; ++i) {
        offs[i] = base;
        cur[i]  = base;
        base += cnt[i];
    }
    if (t == 1023) offs[NN] = base;
}

__global__ void k_scatter4(const int* __restrict__ s0, const int* __restrict__ d0,
                           const int* __restrict__ s1, const int* __restrict__ d1,
                           const int* __restrict__ s2, const int* __restrict__ d2,
                           const int* __restrict__ s3, const int* __restrict__ d3,
                           int* __restrict__ cur, int* __restrict__ ssrc) {
    int e = blockIdx.x * 256 + threadIdx.x;
    int r = blockIdx.y;
    const int* src = r == 0 ? s0 : r == 1 ? s1 : r == 2 ? s2 : s3;
    const int* dst = r == 0 ? d0 : r == 1 ? d1 : r == 2 ? d2 : d3;
    if (e < NE) {
        int v = dst[e];
        int pos = atomicAdd(&cur[r * NN + v], 1);
        ssrc[r * NE + pos] = src[e];
    }
}

// EmbeddingBag(sum, per_sample_weights) + bias + relu. Warp per node.
__global__ void k_embed(const int* __restrict__ idx, const int* __restrict__ offs,
                        const float* __restrict__ wts, const float* __restrict__ table,
                        const float* __restrict__ bias, float* __restrict__ out) {
    int n = blockIdx.x * 8 + (threadIdx.x >> 5);
    if (n >= NN) return;
    int lane = threadIdx.x & 31;
    int s = offs[n], e = offs[n + 1];
    float4 acc = make_float4(0.f, 0.f, 0.f, 0.f);
    for (int base = s; base < e; base += 32) {
        int j = base + lane;
        int id = (j < e) ? idx[j] : 0;
        float w = (j < e) ? wts[j] : 0.f;
        int cnt = min(32, e - base);
#pragma unroll 2
        for (int t = 0; t < cnt; ++t) {
            int   uj = __shfl_sync(0xffffffffu, id, t);
            float wj = __shfl_sync(0xffffffffu, w,  t);
            float4 tv = *(const float4*)&table[(size_t)uj * HD + lane * 4];
            acc.x = fmaf(tv.x, wj, acc.x);
            acc.y = fmaf(tv.y, wj, acc.y);
            acc.z = fmaf(tv.z, wj, acc.z);
            acc.w = fmaf(tv.w, wj, acc.w);
        }
    }
    float4 b4 = *(const float4*)&bias[lane * 4];
    float4 r;
    r.x = fmaxf(acc.x + b4.x, 0.f);
    r.y = fmaxf(acc.y + b4.y, 0.f);
    r.z = fmaxf(acc.z + b4.z, 0.f);
    r.w = fmaxf(acc.w + b4.w, 0.f);
    *(float4*)&out[(size_t)n * HD + lane * 4] = r;
}

// C[n,OUT] = X[n,128] @ W[128,OUT] + Bias, optionally fused LayerNorm(128)+ReLU.
// 128x128 tile, 256 threads, FFMA2 inner loop, double-buffered smem stages.
__global__ __launch_bounds__(256, 2)
void k_gemm(const float* __restrict__ X, const float* __restrict__ W,
            const float* __restrict__ Bias, const float* __restrict__ lng,
            const float* __restrict__ lnb, float* __restrict__ C,
            int n, int OUT, int do_ln) {
    __shared__ float xs[2][32][132];
    __shared__ float ws[2][32][132];
    int row0 = blockIdx.x * 128, col0 = blockIdx.y * 128;
    int tid = threadIdx.x;
    int tx = tid & 15, ty = tid >> 4;

    int xm = tid >> 1, xk = (tid & 1) * 16;
    int wk0 = tid >> 5, wc = (tid & 31) * 4;

    float4 xr[4], wr[4];
    int buf = 0;

    {
        int kb = 0;
#pragma unroll
        for (int q = 0; q < 4; ++q) {
            int row = row0 + xm;
            xr[q] = (row < n) ? *(const float4*)&X[(size_t)row * 128 + kb + xk + q * 4]
                              : make_float4(0.f, 0.f, 0.f, 0.f);
        }
#pragma unroll
        for (int q = 0; q < 4; ++q)
            wr[q] = *(const float4*)&W[(size_t)(kb + wk0 + q * 8) * OUT + col0 + wc];
#pragma unroll
        for (int q = 0; q < 4; ++q) {
            xs[0][xk + q * 4 + 0][xm] = xr[q].x;
            xs[0][xk + q * 4 + 1][xm] = xr[q].y;
            xs[0][xk + q * 4 + 2][xm] = xr[q].z;
            xs[0][xk + q * 4 + 3][xm] = xr[q].w;
            *(float4*)&ws[0][wk0 + q * 8][wc] = wr[q];
        }
    }
    __syncthreads();

    u64 acc2[8][4] = {};
#pragma unroll
    for (int kb = 0; kb < 128; kb += 32) {
        if (kb + 32 < 128) {
            int kn = kb + 32;
#pragma unroll
            for (int q = 0; q < 4; ++q) {
                int row = row0 + xm;
                xr[q] = (row < n) ? *(const float4*)&X[(size_t)row * 128 + kn + xk + q * 4]
                                  : make_float4(0.f, 0.f, 0.f, 0.f);
            }
#pragma unroll
            for (int q = 0; q < 4; ++q)
                wr[q] = *(const float4*)&W[(size_t)(kn + wk0 + q * 8) * OUT + col0 + wc];
        }
#pragma unroll
        for (int k = 0; k < 32; ++k) {
            float4 a0 = *(const float4*)&xs[buf][k][ty * 4];
            float4 a1 = *(const float4*)&xs[buf][k][64 + ty * 4];
            const u64* bp0 = (const u64*)&ws[buf][k][tx * 4];
            const u64* bp1 = (const u64*)&ws[buf][k][64 + tx * 4];
            u64 b01 = bp0[0], b23 = bp0[1];
            u64 b45 = bp1[0], b67 = bp1[1];
            float av[8] = {a0.x, a0.y, a0.z, a0.w, a1.x, a1.y, a1.z, a1.w};
#pragma unroll
            for (int i = 0; i < 8; ++i) {
                u64 aa = pack2(av[i], av[i]);
                acc2[i][0] = fma2(aa, b01, acc2[i][0]);
                acc2[i][1] = fma2(aa, b23, acc2[i][1]);
                acc2[i][2] = fma2(aa, b45, acc2[i][2]);
                acc2[i][3] = fma2(aa, b67, acc2[i][3]);
            }
        }
        if (kb + 32 < 128) {
            int nb = buf ^ 1;
#pragma unroll
            for (int q = 0; q < 4; ++q) {
                xs[nb][xk + q * 4 + 0][xm] = xr[q].x;
                xs[nb][xk + q * 4 + 1][xm] = xr[q].y;
                xs[nb][xk + q * 4 + 2][xm] = xr[q].z;
                xs[nb][xk + q * 4 + 3][xm] = xr[q].w;
                *(float4*)&ws[nb][wk0 + q * 8][wc] = wr[q];
            }
            __syncthreads();
            buf = nb;
        }
    }

    float acc[8][8];
#pragma unroll
    for (int i = 0; i < 8; ++i)
#pragma unroll
        for (int q = 0; q < 4; ++q)
            unpack2(acc2[i][q], acc[i][q * 2], acc[i][q * 2 + 1]);

    float pb[8];
#pragma unroll
    for (int j = 0; j < 8; ++j) {
        int col = col0 + (j < 4 ? tx * 4 + j : 64 + tx * 4 + j - 4);
        pb[j] = Bias[col];
    }
#pragma unroll
    for (int i = 0; i < 8; ++i)
#pragma unroll
        for (int j = 0; j < 8; ++j) acc[i][j] += pb[j];

    if (do_ln) {
        float gv[8], b2[8];
#pragma unroll
        for (int j = 0; j < 8; ++j) {
            int col = (j < 4 ? tx * 4 + j : 64 + tx * 4 + j - 4);
            gv[j] = lng[col]; b2[j] = lnb[col];
        }
#pragma unroll
        for (int i = 0; i < 8; ++i) {
            float s = 0.f;
#pragma unroll
            for (int j = 0; j < 8; ++j) s += acc[i][j];
#pragma unroll
            for (int o = 1; o < 16; o <<= 1) s += __shfl_xor_sync(0xffffffffu, s, o);
            float mu = s * (1.f / 128.f);
            float q = 0.f;
#pragma unroll
            for (int j = 0; j < 8; ++j) { float d = acc[i][j] - mu; q += d * d; }
#pragma unroll
            for (int o = 1; o < 16; o <<= 1) q += __shfl_xor_sync(0xffffffffu, q, o);
            float rs = rsqrtf(q * (1.f / 128.f) + LN_EPS);
#pragma unroll
            for (int j = 0; j < 8; ++j)
                acc[i][j] = fmaxf((acc[i][j] - mu) * rs * gv[j] + b2[j], 0.f);
        }
    }
#pragma unroll
    for (int i = 0; i < 8; ++i) {
        int row = row0 + (i < 4 ? ty * 4 + i : 64 + ty * 4 + i - 4);
        if (row < n) {
            float4 o0 = make_float4(acc[i][0], acc[i][1], acc[i][2], acc[i][3]);
            float4 o1 = make_float4(acc[i][4], acc[i][5], acc[i][6], acc[i][7]);
            *(float4*)&C[(size_t)row * OUT + col0 + tx * 4]      = o0;
            *(float4*)&C[(size_t)row * OUT + col0 + 64 + tx * 4] = o1;
        }
    }
}

// ---------------- fused per-destination prop kernel ----------------
// TWO warps per node — one per relation — to halve the serial edge chain.
// Each warp runs its relation's single-pass online-softmax loop; the rel-1
// warp deposits its normalized contribution in smem; the rel-0 warp merges
// and performs the elu-residual (h) and normalize/flag (yh) epilogues.
// NN % 4 == 0, so every block has 4 full nodes (uniform __syncthreads).
__global__ __launch_bounds__(256)
void k_prop(const float* __restrict__ f, const float* __restrict__ x,
            const float* __restrict__ yin, const float* __restrict__ attn,
            const int* __restrict__ offp, const int* __restrict__ sp,
            const int* __restrict__ offs2, const int* __restrict__ ss,
            const void* __restrict__ flag,
            float* __restrict__ hout, float* __restrict__ yout) {
    __shared__ float4 s_tf[4][32];
    __shared__ float4 s_y0[4][32];
    __shared__ float4 s_y1[4][32];

    int warp = threadIdx.x >> 5;
    int nib  = warp >> 1;                 // node index within block, 0..3
    int rel  = warp & 1;
    int v    = blockIdx.x * 4 + nib;
    int lane = threadIdx.x & 31;

    float4 at = *(const float4*)&attn[lane * 4];
    u64 at06_0 = pack2(0.6f * at.x, 0.6f * at.y);
    u64 at06_1 = pack2(0.6f * at.z, 0.6f * at.w);
    u64 at04_0 = pack2(0.4f * at.x, 0.4f * at.y);
    u64 at04_1 = pack2(0.4f * at.z, 0.4f * at.w);
    ulonglong2 fv2 = *(const ulonglong2*)&f[(size_t)v * HD + lane * 4];

    const int* off  = rel ? offs2 : offp;
    const int* ssrc = rel ? ss    : sp;
    int lo = off[v], hi = off[v + 1];

    float m   = -__int_as_float(0x7f800000);
    float den = 0.f;
    u64 af0 = 0, af1 = 0, a00 = 0, a01 = 0, a10 = 0, a11 = 0;

    for (int base = lo; base < hi; base += 32) {
        int j = base + lane;
        int myu = (j < hi) ? __ldg(&ssrc[j]) : 0;
        int cnt = min(32, hi - base);
#pragma unroll 2
        for (int t = 0; t < cnt; ++t) {
            int u = __shfl_sync(0xffffffffu, myu, t);
            ulonglong2 fu = *(const ulonglong2*)&f[(size_t)u * HD + lane * 4];
            ulonglong2 y0 = *(const ulonglong2*)&yin[(size_t)u * OD + lane * 4];
            ulonglong2 y1 = *(const ulonglong2*)&yin[(size_t)u * OD + 128 + lane * 4];
            u64 z0 = add2(fu.x, fv2.x);
            u64 z1 = add2(fu.y, fv2.y);
            u64 p2 = mul2(z0, at06_0);
            p2 = fma2(abs2(z0), at04_0, p2);
            p2 = fma2(z1, at06_1, p2);
            p2 = fma2(abs2(z1), at04_1, p2);
            float px, py;
            unpack2(p2, px, py);
            float p = px + py;
#pragma unroll
            for (int o = 16; o; o >>= 1) p += __shfl_xor_sync(0xffffffffu, p, o);
            if (p > m) {
                float r = __expf(m - p);   // 0 on first edge (m = -inf)
                den *= r;
                u64 r2 = pack2(r, r);
                af0 = mul2(af0, r2); af1 = mul2(af1, r2);
                a00 = mul2(a00, r2); a01 = mul2(a01, r2);
                a10 = mul2(a10, r2); a11 = mul2(a11, r2);
                m = p;
            }
            float w = __expf(p - m);
            den += w;
            u64 w2 = pack2(w, w);
            af0 = fma2(fu.x, w2, af0); af1 = fma2(fu.y, w2, af1);
            a00 = fma2(y0.x, w2, a00); a01 = fma2(y0.y, w2, a01);
            a10 = fma2(y1.x, w2, a10); a11 = fma2(y1.y, w2, a11);
        }
    }

    // normalized per-relation contribution (12 floats per lane)
    float rden = (den > 0.f) ? 1.f / den : 0.f;
    float4 tf, ty0, ty1;
    unpack2(af0, tf.x,  tf.y);  unpack2(af1, tf.z,  tf.w);
    unpack2(a00, ty0.x, ty0.y); unpack2(a01, ty0.z, ty0.w);
    unpack2(a10, ty1.x, ty1.y); unpack2(a11, ty1.z, ty1.w);
    tf.x  *= rden; tf.y  *= rden; tf.z  *= rden; tf.w  *= rden;
    ty0.x *= rden; ty0.y *= rden; ty0.z *= rden; ty0.w *= rden;
    ty1.x *= rden; ty1.y *= rden; ty1.z *= rden; ty1.w *= rden;

    if (rel == 1) {
        s_tf[nib][lane] = tf;
        s_y0[nib][lane] = ty0;
        s_y1[nib][lane] = ty1;
    }
    __syncthreads();
    if (rel == 1) return;

    float4 o_tf = s_tf[nib][lane];
    float4 o_y0 = s_y0[nib][lane];
    float4 o_y1 = s_y1[nib][lane];
    tf.x  += o_tf.x; tf.y  += o_tf.y; tf.z  += o_tf.z; tf.w  += o_tf.w;
    ty0.x += o_y0.x; ty0.y += o_y0.y; ty0.z += o_y0.z; ty0.w += o_y0.w;
    ty1.x += o_y1.x; ty1.y += o_y1.y; ty1.z += o_y1.z; ty1.w += o_y1.w;

    // h epilogue: elu(agg_p + agg_s + 2*x)
    float4 xv = *(const float4*)&x[(size_t)v * HD + lane * 4];
    float4 h;
    h.x = tf.x + 2.f * xv.x; h.x = h.x > 0.f ? h.x : expm1f(h.x);
    h.y = tf.y + 2.f * xv.y; h.y = h.y > 0.f ? h.y : expm1f(h.y);
    h.z = tf.z + 2.f * xv.z; h.z = h.z > 0.f ? h.z : expm1f(h.z);
    h.w = tf.w + 2.f * xv.w; h.w = h.w > 0.f ? h.w : expm1f(h.w);
    *(float4*)&hout[(size_t)v * HD + lane * 4] = h;

    // y epilogue: normalize or copy per flag
    float q = ty0.x * ty0.x + ty0.y * ty0.y + ty0.z * ty0.z + ty0.w * ty0.w
            + ty1.x * ty1.x + ty1.y * ty1.y + ty1.z * ty1.z + ty1.w * ty1.w;
#pragma unroll
    for (int o = 16; o; o >>= 1) q += __shfl_xor_sync(0xffffffffu, q, o);
    float inv = 1.f / fmaxf(sqrtf(q), 1e-12f);
    bool fl;
    if (g_flagIsInt) fl = ((const int*)flag)[v] != 0;
    else             fl = ((const unsigned char*)flag)[v] != 0;
    size_t base = (size_t)v * OD + lane * 4;
    float4 r0, r1;
    if (fl) {
        r0 = *(const float4*)&yin[base];
        r1 = *(const float4*)&yin[base + 128];
    } else {
        r0 = make_float4(ty0.x * inv, ty0.y * inv, ty0.z * inv, ty0.w * inv);
        r1 = make_float4(ty1.x * inv, ty1.y * inv, ty1.z * inv, ty1.w * inv);
    }
    *(float4*)&yout[base]       = r0;
    *(float4*)&yout[base + 128] = r1;
}

// ---------------- host orchestration ----------------
extern "C" void kernel_launch(void* const* d_in, const int* in_sizes, int n_in,
                              void* d_out, int out_size) {
    const int*   emb_indices = (const int*)  d_in[0];
    const int*   emb_offsets = (const int*)  d_in[1];
    const float* emb_weights = (const float*)d_in[2];
    const float* y           = (const float*)d_in[3];
    const void*  flag        = d_in[4];
    const int* src_p1 = (const int*)d_in[5];
    const int* dst_p1 = (const int*)d_in[6];
    const int* src_s1 = (const int*)d_in[7];
    const int* dst_s1 = (const int*)d_in[8];
    const int* src_p2 = (const int*)d_in[9];
    const int* dst_p2 = (const int*)d_in[10];
    const int* src_s2 = (const int*)d_in[11];
    const int* dst_s2 = (const int*)d_in[12];
    const float* embed_W = (const float*)d_in[13];
    const float* embed_b = (const float*)d_in[14];
    const float* mlp_W1  = (const float*)d_in[15];
    const float* mlp_b1  = (const float*)d_in[16];
    const float* ln1_g   = (const float*)d_in[17];
    const float* ln1_b   = (const float*)d_in[18];
    const float* mlp_W2  = (const float*)d_in[19];
    const float* mlp_b2  = (const float*)d_in[20];
    const float* ln2_g   = (const float*)d_in[21];
    const float* ln2_b   = (const float*)d_in[22];
    const float* Wsrc1   = (const float*)d_in[23];
    const float* bsrc1   = (const float*)d_in[24];
    const float* attn1   = (const float*)d_in[25];
    const float* Wsrc2   = (const float*)d_in[26];
    const float* bsrc2   = (const float*)d_in[27];
    const float* attn2   = (const float*)d_in[28];
    const float* out_W   = (const float*)d_in[29];
    const float* out_b   = (const float*)d_in[30];

    float *hA, *hB, *f, *yA;
    int *off, *ssrc, *cnt, *cur;
    cudaGetSymbolAddress((void**)&hA,   g_hA);
    cudaGetSymbolAddress((void**)&hB,   g_hB);
    cudaGetSymbolAddress((void**)&f,    g_f);
    cudaGetSymbolAddress((void**)&yA,   g_yA);
    cudaGetSymbolAddress((void**)&off,  g_off);
    cudaGetSymbolAddress((void**)&ssrc, g_ssrc);
    cudaGetSymbolAddress((void**)&cnt,  g_cnt);
    cudaGetSymbolAddress((void**)&cur,  g_cur);

    float* logits = (float*)d_out;
    float* yh_out = (float*)d_out + (size_t)NN * OD;

    // Side stream for the CSR build (independent of embed+MLP); capture-legal
    // fork/join via events.
    cudaStream_t s2;
    cudaEvent_t ev0, ev1;
    cudaStreamCreateWithFlags(&s2, cudaStreamNonBlocking);
    cudaEventCreateWithFlags(&ev0, cudaEventDisableTiming);
    cudaEventCreateWithFlags(&ev1, cudaEventDisableTiming);

    cudaEventRecord(ev0, 0);

    // ---- main branch: EmbeddingBag + MLP (LN fused) + f-GEMM for prop1 ----
    k_embed<<<(NN + 7) / 8, 256>>>(emb_indices, emb_offsets, emb_weights, embed_W, embed_b, hA);
    dim3 g1((NN + 127) / 128, 1);
    k_gemm<<<g1, 256>>>(hA, mlp_W1, mlp_b1, ln1_g, ln1_b, hB, NN, 128, 1);
    k_gemm<<<g1, 256>>>(hB, mlp_W2, mlp_b2, ln2_g, ln2_b, hA, NN, 128, 1);
    k_gemm<<<g1, 256>>>(hA, Wsrc1, bsrc1, nullptr, nullptr, f, NN, 128, 0);

    // ---- side branch: flag detect + CSR sorts for the 4 relations ----
    cudaStreamWaitEvent(s2, ev0, 0);
    k_detect_flag<<<1, 256, 0, s2>>>((const unsigned char*)flag);
    cudaMemsetAsync(cnt, 0, sizeof(int) * 4 * NN, s2);
    dim3 ge((NE + 255) / 256, 4);
    k_hist4<<<ge, 256, 0, s2>>>(dst_p1, dst_s1, dst_p2, dst_s2, cnt);
    k_scan4<<<4, 1024, 0, s2>>>(cnt, off, cur);
    k_scatter4<<<ge, 256, 0, s2>>>(src_p1, dst_p1, src_s1, dst_s1,
                                   src_p2, dst_p2, src_s2, dst_s2, cur, ssrc);
    cudaEventRecord(ev1, s2);

    // ---- join, then props (2 warps per node => NN/4 blocks) ----
    cudaStreamWaitEvent(0, ev1, 0);
    k_prop<<<NN / 4, 256>>>(f, hA, y, attn1,
                            off + 0 * (NN + 1), ssrc + 0 * NE,
                            off + 1 * (NN + 1), ssrc + 1 * NE,
                            flag, hB, yA);

    k_gemm<<<g1, 256>>>(hB, Wsrc2, bsrc2, nullptr, nullptr, f, NN, 128, 0);
    k_prop<<<NN / 4, 256>>>(f, hB, yA, attn2,
                            off + 2 * (NN + 1), ssrc + 2 * NE,
                            off + 3 * (NN + 1), ssrc + 3 * NE,
                            flag, hA, yh_out);

    // ---- logits = h @ out_W + out_b ----
    dim3 g2((NN + 127) / 128, 2);
    k_gemm<<<g2, 256>>>(hA, out_W, out_b, nullptr, nullptr, logits, NN, 256, 0);
}

// round 12
// speedup vs baseline: 1.0051x; 1.0051x over previous
#include <cuda_runtime.h>
#include <math.h>

#define NN 50000
#define HD 128
#define OD 256
#define NE 800000
#define LN_EPS 1e-5f

typedef unsigned long long u64;

// ---------------- scratch (static device globals; no allocation) ----------------
__device__ float g_hA[NN * HD];
__device__ float g_hB[NN * HD];
__device__ float g_f [NN * HD];
__device__ float g_yA [NN * OD];
__device__ int   g_off [4][NN + 1];
__device__ int   g_ssrc[4][NE];
__device__ int   g_cnt[4][NN];
__device__ int   g_cur[4][NN];
__device__ int   g_flagIsInt;

// ---------------- helpers ----------------
__device__ __forceinline__ u64 pack2(float lo, float hi) {
    u64 r;
    asm("mov.b64 %0, {%1, %2};" : "=l"(r) : "f"(lo), "f"(hi));
    return r;
}
__device__ __forceinline__ void unpack2(u64 v, float& lo, float& hi) {
    asm("mov.b64 {%0, %1}, %2;" : "=f"(lo), "=f"(hi) : "l"(v));
}
__device__ __forceinline__ u64 fma2(u64 a, u64 b, u64 c) {
    u64 d;
    asm("fma.rn.f32x2 %0, %1, %2, %3;" : "=l"(d) : "l"(a), "l"(b), "l"(c));
    return d;
}
__device__ __forceinline__ u64 mul2(u64 a, u64 b) {
    u64 d;
    asm("mul.rn.f32x2 %0, %1, %2;" : "=l"(d) : "l"(a), "l"(b));
    return d;
}
__device__ __forceinline__ u64 add2(u64 a, u64 b) {
    u64 d;
    asm("add.rn.f32x2 %0, %1, %2;" : "=l"(d) : "l"(a), "l"(b));
    return d;
}
__device__ __forceinline__ u64 abs2(u64 a) {
    return a & 0x7FFFFFFF7FFFFFFFULL;
}

// ---------------- kernels ----------------

// Detect flag buffer layout: int32 (bytes 1..3 of each word are 0) vs uint8.
__global__ void k_detect_flag(const unsigned char* __restrict__ flag) {
    __shared__ int cnt;
    if (threadIdx.x == 0) cnt = 0;
    __syncthreads();
    int local = 0;
    for (int i = threadIdx.x; i < 4000; i += 256)
        if ((i & 3) != 0 && flag[i] != 0) local = 1;
    if (local) atomicOr(&cnt, 1);
    __syncthreads();
    if (threadIdx.x == 0) g_flagIsInt = (cnt == 0) ? 1 : 0;
}

// -------- counting sort by dst (all 4 relations in one grid via blockIdx.y) --------
__global__ void k_hist4(const int* __restrict__ d0, const int* __restrict__ d1,
                        const int* __restrict__ d2, const int* __restrict__ d3,
                        int* __restrict__ cnt) {
    int e = blockIdx.x * 256 + threadIdx.x;
    int r = blockIdx.y;
    const int* dst = r == 0 ? d0 : r == 1 ? d1 : r == 2 ? d2 : d3;
    if (e < NE) atomicAdd(&cnt[r * NN + dst[e]], 1);
}

// 4 blocks, one relation each: exclusive scan -> offs[NN+1], cur[NN]
__global__ void k_scan4(const int* __restrict__ cntAll, int* __restrict__ offsAll,
                        int* __restrict__ curAll) {
    __shared__ int part[1024];
    const int CH = (NN + 1023) / 1024;
    int r = blockIdx.x;
    const int* cnt = cntAll + r * NN;
    int* offs = offsAll + r * (NN + 1);
    int* cur  = curAll  + r * NN;
    int t = threadIdx.x;
    int lo = t * CH, hi = min(lo + CH, NN);
    int s = 0;
    for (int i = lo; i < hi; ++i) s += cnt[i];
    part[t] = s;
    __syncthreads();
    for (int o = 1; o < 1024; o <<= 1) {
        int v = (t >= o) ? part[t - o] : 0;
        __syncthreads();
        part[t] += v;
        __syncthreads();
    }
    int base = (t == 0) ? 0 : part[t - 1];
    for (int i = lo; i < hi; ++i) {
        offs[i] = base;
        cur[i]  = base;
        base += cnt[i];
    }
    if (t == 1023) offs[NN] = base;
}

__global__ void k_scatter4(const int* __restrict__ s0, const int* __restrict__ d0,
                           const int* __restrict__ s1, const int* __restrict__ d1,
                           const int* __restrict__ s2, const int* __restrict__ d2,
                           const int* __restrict__ s3, const int* __restrict__ d3,
                           int* __restrict__ cur, int* __restrict__ ssrc) {
    int e = blockIdx.x * 256 + threadIdx.x;
    int r = blockIdx.y;
    const int* src = r == 0 ? s0 : r == 1 ? s1 : r == 2 ? s2 : s3;
    const int* dst = r == 0 ? d0 : r == 1 ? d1 : r == 2 ? d2 : d3;
    if (e < NE) {
        int v = dst[e];
        int pos = atomicAdd(&cur[r * NN + v], 1);
        ssrc[r * NE + pos] = src[e];
    }
}

// EmbeddingBag(sum, per_sample_weights) + bias + relu. Warp per node.
__global__ void k_embed(const int* __restrict__ idx, const int* __restrict__ offs,
                        const float* __restrict__ wts, const float* __restrict__ table,
                        const float* __restrict__ bias, float* __restrict__ out) {
    int n = blockIdx.x * 8 + (threadIdx.x >> 5);
    if (n >= NN) return;
    int lane = threadIdx.x & 31;
    int s = offs[n], e = offs[n + 1];
    float4 acc = make_float4(0.f, 0.f, 0.f, 0.f);
    for (int base = s; base < e; base += 32) {
        int j = base + lane;
        int id = (j < e) ? idx[j] : 0;
        float w = (j < e) ? wts[j] : 0.f;
        int cnt = min(32, e - base);
#pragma unroll 2
        for (int t = 0; t < cnt; ++t) {
            int   uj = __shfl_sync(0xffffffffu, id, t);
            float wj = __shfl_sync(0xffffffffu, w,  t);
            float4 tv = *(const float4*)&table[(size_t)uj * HD + lane * 4];
            acc.x = fmaf(tv.x, wj, acc.x);
            acc.y = fmaf(tv.y, wj, acc.y);
            acc.z = fmaf(tv.z, wj, acc.z);
            acc.w = fmaf(tv.w, wj, acc.w);
        }
    }
    float4 b4 = *(const float4*)&bias[lane * 4];
    float4 r;
    r.x = fmaxf(acc.x + b4.x, 0.f);
    r.y = fmaxf(acc.y + b4.y, 0.f);
    r.z = fmaxf(acc.z + b4.z, 0.f);
    r.w = fmaxf(acc.w + b4.w, 0.f);
    *(float4*)&out[(size_t)n * HD + lane * 4] = r;
}

// C[n,OUT] = X[n,128] @ W[128,OUT] + Bias, optionally fused LayerNorm(128)+ReLU.
// 64x128 tile, 256 threads (4 rows x 8 cols per thread), FFMA2 inner loop,
// double-buffered smem stages, 3 CTAs/SM.
__global__ __launch_bounds__(256, 3)
void k_gemm(const float* __restrict__ X, const float* __restrict__ W,
            const float* __restrict__ Bias, const float* __restrict__ lng,
            const float* __restrict__ lnb, float* __restrict__ C,
            int n, int OUT, int do_ln) {
    __shared__ float xs[2][32][68];    // [k][row], 64 rows
    __shared__ float ws[2][32][132];   // [k][col], 128 cols
    int row0 = blockIdx.x * 64, col0 = blockIdx.y * 128;
    int tid = threadIdx.x;
    int tx = tid & 15, ty = tid >> 4;

    // per-thread load coordinates
    int xm = tid >> 2, xk = (tid & 3) * 8;   // X: row xm, k pair [xk, xk+4)
    int wk0 = tid >> 5, wc = (tid & 31) * 4; // W: rows wk0+{0,8,16,24}, col wc

    float4 xr[2], wr[4];
    int buf = 0;

    // prologue: load stage 0
    {
        int row = row0 + xm;
#pragma unroll
        for (int q = 0; q < 2; ++q)
            xr[q] = (row < n) ? *(const float4*)&X[(size_t)row * 128 + xk + q * 4]
                              : make_float4(0.f, 0.f, 0.f, 0.f);
#pragma unroll
        for (int q = 0; q < 4; ++q)
            wr[q] = *(const float4*)&W[(size_t)(wk0 + q * 8) * OUT + col0 + wc];
#pragma unroll
        for (int q = 0; q < 2; ++q) {
            xs[0][xk + q * 4 + 0][xm] = xr[q].x;
            xs[0][xk + q * 4 + 1][xm] = xr[q].y;
            xs[0][xk + q * 4 + 2][xm] = xr[q].z;
            xs[0][xk + q * 4 + 3][xm] = xr[q].w;
        }
#pragma unroll
        for (int q = 0; q < 4; ++q)
            *(float4*)&ws[0][wk0 + q * 8][wc] = wr[q];
    }
    __syncthreads();

    u64 acc2[4][4] = {};
#pragma unroll
    for (int kb = 0; kb < 128; kb += 32) {
        if (kb + 32 < 128) {
            int kn = kb + 32;
            int row = row0 + xm;
#pragma unroll
            for (int q = 0; q < 2; ++q)
                xr[q] = (row < n) ? *(const float4*)&X[(size_t)row * 128 + kn + xk + q * 4]
                                  : make_float4(0.f, 0.f, 0.f, 0.f);
#pragma unroll
            for (int q = 0; q < 4; ++q)
                wr[q] = *(const float4*)&W[(size_t)(kn + wk0 + q * 8) * OUT + col0 + wc];
        }
#pragma unroll
        for (int k = 0; k < 32; ++k) {
            float4 a0 = *(const float4*)&xs[buf][k][ty * 4];
            const u64* bp0 = (const u64*)&ws[buf][k][tx * 4];
            const u64* bp1 = (const u64*)&ws[buf][k][64 + tx * 4];
            u64 b01 = bp0[0], b23 = bp0[1];
            u64 b45 = bp1[0], b67 = bp1[1];
            float av[4] = {a0.x, a0.y, a0.z, a0.w};
#pragma unroll
            for (int i = 0; i < 4; ++i) {
                u64 aa = pack2(av[i], av[i]);
                acc2[i][0] = fma2(aa, b01, acc2[i][0]);
                acc2[i][1] = fma2(aa, b23, acc2[i][1]);
                acc2[i][2] = fma2(aa, b45, acc2[i][2]);
                acc2[i][3] = fma2(aa, b67, acc2[i][3]);
            }
        }
        if (kb + 32 < 128) {
            int nb = buf ^ 1;
#pragma unroll
            for (int q = 0; q < 2; ++q) {
                xs[nb][xk + q * 4 + 0][xm] = xr[q].x;
                xs[nb][xk + q * 4 + 1][xm] = xr[q].y;
                xs[nb][xk + q * 4 + 2][xm] = xr[q].z;
                xs[nb][xk + q * 4 + 3][xm] = xr[q].w;
            }
#pragma unroll
            for (int q = 0; q < 4; ++q)
                *(float4*)&ws[nb][wk0 + q * 8][wc] = wr[q];
            __syncthreads();
            buf = nb;
        }
    }

    float acc[4][8];
#pragma unroll
    for (int i = 0; i < 4; ++i)
#pragma unroll
        for (int q = 0; q < 4; ++q)
            unpack2(acc2[i][q], acc[i][q * 2], acc[i][q * 2 + 1]);

    // bias add
    float pb[8];
#pragma unroll
    for (int j = 0; j < 8; ++j) {
        int col = col0 + (j < 4 ? tx * 4 + j : 64 + tx * 4 + j - 4);
        pb[j] = Bias[col];
    }
#pragma unroll
    for (int i = 0; i < 4; ++i)
#pragma unroll
        for (int j = 0; j < 8; ++j) acc[i][j] += pb[j];

    if (do_ln) {  // OUT must be 128: the 16 tx lanes of each half-warp hold a full row
        float gv[8], b2[8];
#pragma unroll
        for (int j = 0; j < 8; ++j) {
            int col = (j < 4 ? tx * 4 + j : 64 + tx * 4 + j - 4);
            gv[j] = lng[col]; b2[j] = lnb[col];
        }
#pragma unroll
        for (int i = 0; i < 4; ++i) {
            float s = 0.f;
#pragma unroll
            for (int j = 0; j < 8; ++j) s += acc[i][j];
#pragma unroll
            for (int o = 1; o < 16; o <<= 1) s += __shfl_xor_sync(0xffffffffu, s, o);
            float mu = s * (1.f / 128.f);
            float q = 0.f;
#pragma unroll
            for (int j = 0; j < 8; ++j) { float d = acc[i][j] - mu; q += d * d; }
#pragma unroll
            for (int o = 1; o < 16; o <<= 1) q += __shfl_xor_sync(0xffffffffu, q, o);
            float rs = rsqrtf(q * (1.f / 128.f) + LN_EPS);
#pragma unroll
            for (int j = 0; j < 8; ++j)
                acc[i][j] = fmaxf((acc[i][j] - mu) * rs * gv[j] + b2[j], 0.f);
        }
    }
#pragma unroll
    for (int i = 0; i < 4; ++i) {
        int row = row0 + ty * 4 + i;
        if (row < n) {
            float4 o0 = make_float4(acc[i][0], acc[i][1], acc[i][2], acc[i][3]);
            float4 o1 = make_float4(acc[i][4], acc[i][5], acc[i][6], acc[i][7]);
            *(float4*)&C[(size_t)row * OUT + col0 + tx * 4]      = o0;
            *(float4*)&C[(size_t)row * OUT + col0 + 64 + tx * 4] = o1;
        }
    }
}

// ---------------- fused per-destination prop kernel (R10 winner, reverted) ----
// Warp per dst node; single-pass online-softmax GAT + label prop, f32x2 math.
__global__ void k_prop(const float* __restrict__ f, const float* __restrict__ x,
                       const float* __restrict__ yin, const float* __restrict__ attn,
                       const int* __restrict__ offp, const int* __restrict__ sp,
                       const int* __restrict__ offs2, const int* __restrict__ ss,
                       const void* __restrict__ flag,
                       float* __restrict__ hout, float* __restrict__ yout) {
    int v = blockIdx.x * 8 + (threadIdx.x >> 5);
    if (v >= NN) return;
    int lane = threadIdx.x & 31;

    float4 at = *(const float4*)&attn[lane * 4];
    u64 at06_0 = pack2(0.6f * at.x, 0.6f * at.y);
    u64 at06_1 = pack2(0.6f * at.z, 0.6f * at.w);
    u64 at04_0 = pack2(0.4f * at.x, 0.4f * at.y);
    u64 at04_1 = pack2(0.4f * at.z, 0.4f * at.w);
    ulonglong2 fv2 = *(const ulonglong2*)&f[(size_t)v * HD + lane * 4];

    float4 tf  = make_float4(0.f, 0.f, 0.f, 0.f);
    float4 ty0 = make_float4(0.f, 0.f, 0.f, 0.f);
    float4 ty1 = make_float4(0.f, 0.f, 0.f, 0.f);

#pragma unroll
    for (int rel = 0; rel < 2; ++rel) {
        const int* off  = rel ? offs2 : offp;
        const int* ssrc = rel ? ss    : sp;
        int lo = off[v], hi = off[v + 1];

        float m   = -__int_as_float(0x7f800000);
        float den = 0.f;
        u64 af0 = 0, af1 = 0, a00 = 0, a01 = 0, a10 = 0, a11 = 0;

        for (int base = lo; base < hi; base += 32) {
            int j = base + lane;
            int myu = (j < hi) ? __ldg(&ssrc[j]) : 0;
            int cnt = min(32, hi - base);
#pragma unroll 2
            for (int t = 0; t < cnt; ++t) {
                int u = __shfl_sync(0xffffffffu, myu, t);
                ulonglong2 fu = *(const ulonglong2*)&f[(size_t)u * HD + lane * 4];
                ulonglong2 y0 = *(const ulonglong2*)&yin[(size_t)u * OD + lane * 4];
                ulonglong2 y1 = *(const ulonglong2*)&yin[(size_t)u * OD + 128 + lane * 4];
                u64 z0 = add2(fu.x, fv2.x);
                u64 z1 = add2(fu.y, fv2.y);
                u64 p2 = mul2(z0, at06_0);
                p2 = fma2(abs2(z0), at04_0, p2);
                p2 = fma2(z1, at06_1, p2);
                p2 = fma2(abs2(z1), at04_1, p2);
                float px, py;
                unpack2(p2, px, py);
                float p = px + py;
#pragma unroll
                for (int o = 16; o; o >>= 1) p += __shfl_xor_sync(0xffffffffu, p, o);
                if (p > m) {
                    float r = __expf(m - p);   // 0 on first edge (m = -inf)
                    den *= r;
                    u64 r2 = pack2(r, r);
                    af0 = mul2(af0, r2); af1 = mul2(af1, r2);
                    a00 = mul2(a00, r2); a01 = mul2(a01, r2);
                    a10 = mul2(a10, r2); a11 = mul2(a11, r2);
                    m = p;
                }
                float w = __expf(p - m);
                den += w;
                u64 w2 = pack2(w, w);
                af0 = fma2(fu.x, w2, af0); af1 = fma2(fu.y, w2, af1);
                a00 = fma2(y0.x, w2, a00); a01 = fma2(y0.y, w2, a01);
                a10 = fma2(y1.x, w2, a10); a11 = fma2(y1.y, w2, a11);
            }
        }
        float rden = (den > 0.f) ? 1.f / den : 0.f;
        float e0, e1;
        unpack2(af0, e0, e1); tf.x  = fmaf(e0, rden, tf.x);  tf.y  = fmaf(e1, rden, tf.y);
        unpack2(af1, e0, e1); tf.z  = fmaf(e0, rden, tf.z);  tf.w  = fmaf(e1, rden, tf.w);
        unpack2(a00, e0, e1); ty0.x = fmaf(e0, rden, ty0.x); ty0.y = fmaf(e1, rden, ty0.y);
        unpack2(a01, e0, e1); ty0.z = fmaf(e0, rden, ty0.z); ty0.w = fmaf(e1, rden, ty0.w);
        unpack2(a10, e0, e1); ty1.x = fmaf(e0, rden, ty1.x); ty1.y = fmaf(e1, rden, ty1.y);
        unpack2(a11, e0, e1); ty1.z = fmaf(e0, rden, ty1.z); ty1.w = fmaf(e1, rden, ty1.w);
    }

    // h epilogue: elu(agg_p + agg_s + 2*x)
    float4 xv = *(const float4*)&x[(size_t)v * HD + lane * 4];
    float4 h;
    h.x = tf.x + 2.f * xv.x; h.x = h.x > 0.f ? h.x : expm1f(h.x);
    h.y = tf.y + 2.f * xv.y; h.y = h.y > 0.f ? h.y : expm1f(h.y);
    h.z = tf.z + 2.f * xv.z; h.z = h.z > 0.f ? h.z : expm1f(h.z);
    h.w = tf.w + 2.f * xv.w; h.w = h.w > 0.f ? h.w : expm1f(h.w);
    *(float4*)&hout[(size_t)v * HD + lane * 4] = h;

    // y epilogue: normalize or copy per flag
    float q = ty0.x * ty0.x + ty0.y * ty0.y + ty0.z * ty0.z + ty0.w * ty0.w
            + ty1.x * ty1.x + ty1.y * ty1.y + ty1.z * ty1.z + ty1.w * ty1.w;
#pragma unroll
    for (int o = 16; o; o >>= 1) q += __shfl_xor_sync(0xffffffffu, q, o);
    float inv = 1.f / fmaxf(sqrtf(q), 1e-12f);
    bool fl;
    if (g_flagIsInt) fl = ((const int*)flag)[v] != 0;
    else             fl = ((const unsigned char*)flag)[v] != 0;
    size_t base = (size_t)v * OD + lane * 4;
    float4 r0, r1;
    if (fl) {
        r0 = *(const float4*)&yin[base];
        r1 = *(const float4*)&yin[base + 128];
    } else {
        r0 = make_float4(ty0.x * inv, ty0.y * inv, ty0.z * inv, ty0.w * inv);
        r1 = make_float4(ty1.x * inv, ty1.y * inv, ty1.z * inv, ty1.w * inv);
    }
    *(float4*)&yout[base]       = r0;
    *(float4*)&yout[base + 128] = r1;
}

// ---------------- host orchestration ----------------
extern "C" void kernel_launch(void* const* d_in, const int* in_sizes, int n_in,
                              void* d_out, int out_size) {
    const int*   emb_indices = (const int*)  d_in[0];
    const int*   emb_offsets = (const int*)  d_in[1];
    const float* emb_weights = (const float*)d_in[2];
    const float* y           = (const float*)d_in[3];
    const void*  flag        = d_in[4];
    const int* src_p1 = (const int*)d_in[5];
    const int* dst_p1 = (const int*)d_in[6];
    const int* src_s1 = (const int*)d_in[7];
    const int* dst_s1 = (const int*)d_in[8];
    const int* src_p2 = (const int*)d_in[9];
    const int* dst_p2 = (const int*)d_in[10];
    const int* src_s2 = (const int*)d_in[11];
    const int* dst_s2 = (const int*)d_in[12];
    const float* embed_W = (const float*)d_in[13];
    const float* embed_b = (const float*)d_in[14];
    const float* mlp_W1  = (const float*)d_in[15];
    const float* mlp_b1  = (const float*)d_in[16];
    const float* ln1_g   = (const float*)d_in[17];
    const float* ln1_b   = (const float*)d_in[18];
    const float* mlp_W2  = (const float*)d_in[19];
    const float* mlp_b2  = (const float*)d_in[20];
    const float* ln2_g   = (const float*)d_in[21];
    const float* ln2_b   = (const float*)d_in[22];
    const float* Wsrc1   = (const float*)d_in[23];
    const float* bsrc1   = (const float*)d_in[24];
    const float* attn1   = (const float*)d_in[25];
    const float* Wsrc2   = (const float*)d_in[26];
    const float* bsrc2   = (const float*)d_in[27];
    const float* attn2   = (const float*)d_in[28];
    const float* out_W   = (const float*)d_in[29];
    const float* out_b   = (const float*)d_in[30];

    float *hA, *hB, *f, *yA;
    int *off, *ssrc, *cnt, *cur;
    cudaGetSymbolAddress((void**)&hA,   g_hA);
    cudaGetSymbolAddress((void**)&hB,   g_hB);
    cudaGetSymbolAddress((void**)&f,    g_f);
    cudaGetSymbolAddress((void**)&yA,   g_yA);
    cudaGetSymbolAddress((void**)&off,  g_off);
    cudaGetSymbolAddress((void**)&ssrc, g_ssrc);
    cudaGetSymbolAddress((void**)&cnt,  g_cnt);
    cudaGetSymbolAddress((void**)&cur,  g_cur);

    float* logits = (float*)d_out;
    float* yh_out = (float*)d_out + (size_t)NN * OD;

    // Side stream for the CSR build (independent of embed+MLP); capture-legal
    // fork/join via events.
    cudaStream_t s2;
    cudaEvent_t ev0, ev1;
    cudaStreamCreateWithFlags(&s2, cudaStreamNonBlocking);
    cudaEventCreateWithFlags(&ev0, cudaEventDisableTiming);
    cudaEventCreateWithFlags(&ev1, cudaEventDisableTiming);

    cudaEventRecord(ev0, 0);

    // ---- main branch: EmbeddingBag + MLP (LN fused) + f-GEMM for prop1 ----
    k_embed<<<(NN + 7) / 8, 256>>>(emb_indices, emb_offsets, emb_weights, embed_W, embed_b, hA);
    dim3 g1((NN + 63) / 64, 1);
    k_gemm<<<g1, 256>>>(hA, mlp_W1, mlp_b1, ln1_g, ln1_b, hB, NN, 128, 1);
    k_gemm<<<g1, 256>>>(hB, mlp_W2, mlp_b2, ln2_g, ln2_b, hA, NN, 128, 1);
    k_gemm<<<g1, 256>>>(hA, Wsrc1, bsrc1, nullptr, nullptr, f, NN, 128, 0);

    // ---- side branch: flag detect + CSR sorts for the 4 relations ----
    cudaStreamWaitEvent(s2, ev0, 0);
    k_detect_flag<<<1, 256, 0, s2>>>((const unsigned char*)flag);
    cudaMemsetAsync(cnt, 0, sizeof(int) * 4 * NN, s2);
    dim3 ge((NE + 255) / 256, 4);
    k_hist4<<<ge, 256, 0, s2>>>(dst_p1, dst_s1, dst_p2, dst_s2, cnt);
    k_scan4<<<4, 1024, 0, s2>>>(cnt, off, cur);
    k_scatter4<<<ge, 256, 0, s2>>>(src_p1, dst_p1, src_s1, dst_s1,
                                   src_p2, dst_p2, src_s2, dst_s2, cur, ssrc);
    cudaEventRecord(ev1, s2);

    // ---- join, then props ----
    cudaStreamWaitEvent(0, ev1, 0);
    k_prop<<<(NN + 7) / 8, 256>>>(f, hA, y, attn1,
                                  off + 0 * (NN + 1), ssrc + 0 * NE,
                                  off + 1 * (NN + 1), ssrc + 1 * NE,
                                  flag, hB, yA);

    k_gemm<<<g1, 256>>>(hB, Wsrc2, bsrc2, nullptr, nullptr, f, NN, 128, 0);
    k_prop<<<(NN + 7) / 8, 256>>>(f, hB, yA, attn2,
                                  off + 2 * (NN + 1), ssrc + 2 * NE,
                                  off + 3 * (NN + 1), ssrc + 3 * NE,
                                  flag, hA, yh_out);

    // ---- logits = h @ out_W + out_b ----
    dim3 g2((NN + 63) / 64, 2);
    k_gemm<<<g2, 256>>>(hA, out_W, out_b, nullptr, nullptr, logits, NN, 256, 0);
}

// round 13
// speedup vs baseline: 1.0481x; 1.0428x over previous
#include <cuda_runtime.h>
#include <cuda_fp16.h>
#include <math.h>

#define NN 50000
#define HD 128
#define OD 256
#define NE 800000
#define LN_EPS 1e-5f

typedef unsigned long long u64;

// ---------------- scratch (static device globals; no allocation) ----------------
__device__ float  g_hA[NN * HD];
__device__ float  g_hB[NN * HD];
__device__ float  g_f [NN * HD];
__device__ float  g_yA [NN * OD];
__device__ __half g_yA16[NN * OD];
__device__ int    g_off [4][NN + 1];
__device__ int    g_ssrc[4][NE];
__device__ int    g_cnt[4][NN];
__device__ int    g_cur[4][NN];
__device__ int    g_flagIsInt;

// ---------------- helpers ----------------
__device__ __forceinline__ u64 pack2(float lo, float hi) {
    u64 r;
    asm("mov.b64 %0, {%1, %2};" : "=l"(r) : "f"(lo), "f"(hi));
    return r;
}
__device__ __forceinline__ void unpack2(u64 v, float& lo, float& hi) {
    asm("mov.b64 {%0, %1}, %2;" : "=f"(lo), "=f"(hi) : "l"(v));
}
__device__ __forceinline__ u64 fma2(u64 a, u64 b, u64 c) {
    u64 d;
    asm("fma.rn.f32x2 %0, %1, %2, %3;" : "=l"(d) : "l"(a), "l"(b), "l"(c));
    return d;
}
__device__ __forceinline__ u64 mul2(u64 a, u64 b) {
    u64 d;
    asm("mul.rn.f32x2 %0, %1, %2;" : "=l"(d) : "l"(a), "l"(b));
    return d;
}
__device__ __forceinline__ u64 add2(u64 a, u64 b) {
    u64 d;
    asm("add.rn.f32x2 %0, %1, %2;" : "=l"(d) : "l"(a), "l"(b));
    return d;
}
__device__ __forceinline__ u64 abs2(u64 a) {
    return a & 0x7FFFFFFF7FFFFFFFULL;
}

// ---------------- kernels ----------------

// Detect flag buffer layout: int32 (bytes 1..3 of each word are 0) vs uint8.
__global__ void k_detect_flag(const unsigned char* __restrict__ flag) {
    __shared__ int cnt;
    if (threadIdx.x == 0) cnt = 0;
    __syncthreads();
    int local = 0;
    for (int i = threadIdx.x; i < 4000; i += 256)
        if ((i & 3) != 0 && flag[i] != 0) local = 1;
    if (local) atomicOr(&cnt, 1);
    __syncthreads();
    if (threadIdx.x == 0) g_flagIsInt = (cnt == 0) ? 1 : 0;
}

// -------- counting sort by dst (all 4 relations in one grid via blockIdx.y) --------
__global__ void k_hist4(const int* __restrict__ d0, const int* __restrict__ d1,
                        const int* __restrict__ d2, const int* __restrict__ d3,
                        int* __restrict__ cnt) {
    int e = blockIdx.x * 256 + threadIdx.x;
    int r = blockIdx.y;
    const int* dst = r == 0 ? d0 : r == 1 ? d1 : r == 2 ? d2 : d3;
    if (e < NE) atomicAdd(&cnt[r * NN + dst[e]], 1);
}

// 4 blocks, one relation each: exclusive scan -> offs[NN+1], cur[NN]
__global__ void k_scan4(const int* __restrict__ cntAll, int* __restrict__ offsAll,
                        int* __restrict__ curAll) {
    __shared__ int part[1024];
    const int CH = (NN + 1023) / 1024;
    int r = blockIdx.x;
    const int* cnt = cntAll + r * NN;
    int* offs = offsAll + r * (NN + 1);
    int* cur  = curAll  + r * NN;
    int t = threadIdx.x;
    int lo = t * CH, hi = min(lo + CH, NN);
    int s = 0;
    for (int i = lo; i < hi; ++i) s += cnt[i];
    part[t] = s;
    __syncthreads();
    for (int o = 1; o < 1024; o <<= 1) {
        int v = (t >= o) ? part[t - o] : 0;
        __syncthreads();
        part[t] += v;
        __syncthreads();
    }
    int base = (t == 0) ? 0 : part[t - 1];
    for (int i = lo; i < hi; ++i) {
        offs[i] = base;
        cur[i]  = base;
        base += cnt[i];
    }
    if (t == 1023) offs[NN] = base;
}

__global__ void k_scatter4(const int* __restrict__ s0, const int* __restrict__ d0,
                           const int* __restrict__ s1, const int* __restrict__ d1,
                           const int* __restrict__ s2, const int* __restrict__ d2,
                           const int* __restrict__ s3, const int* __restrict__ d3,
                           int* __restrict__ cur, int* __restrict__ ssrc) {
    int e = blockIdx.x * 256 + threadIdx.x;
    int r = blockIdx.y;
    const int* src = r == 0 ? s0 : r == 1 ? s1 : r == 2 ? s2 : s3;
    const int* dst = r == 0 ? d0 : r == 1 ? d1 : r == 2 ? d2 : d3;
    if (e < NE) {
        int v = dst[e];
        int pos = atomicAdd(&cur[r * NN + v], 1);
        ssrc[r * NE + pos] = src[e];
    }
}

// EmbeddingBag(sum, per_sample_weights) + bias + relu. Warp per node.
__global__ void k_embed(const int* __restrict__ idx, const int* __restrict__ offs,
                        const float* __restrict__ wts, const float* __restrict__ table,
                        const float* __restrict__ bias, float* __restrict__ out) {
    int n = blockIdx.x * 8 + (threadIdx.x >> 5);
    if (n >= NN) return;
    int lane = threadIdx.x & 31;
    int s = offs[n], e = offs[n + 1];
    float4 acc = make_float4(0.f, 0.f, 0.f, 0.f);
    for (int base = s; base < e; base += 32) {
        int j = base + lane;
        int id = (j < e) ? idx[j] : 0;
        float w = (j < e) ? wts[j] : 0.f;
        int cnt = min(32, e - base);
#pragma unroll 2
        for (int t = 0; t < cnt; ++t) {
            int   uj = __shfl_sync(0xffffffffu, id, t);
            float wj = __shfl_sync(0xffffffffu, w,  t);
            float4 tv = *(const float4*)&table[(size_t)uj * HD + lane * 4];
            acc.x = fmaf(tv.x, wj, acc.x);
            acc.y = fmaf(tv.y, wj, acc.y);
            acc.z = fmaf(tv.z, wj, acc.z);
            acc.w = fmaf(tv.w, wj, acc.w);
        }
    }
    float4 b4 = *(const float4*)&bias[lane * 4];
    float4 r;
    r.x = fmaxf(acc.x + b4.x, 0.f);
    r.y = fmaxf(acc.y + b4.y, 0.f);
    r.z = fmaxf(acc.z + b4.z, 0.f);
    r.w = fmaxf(acc.w + b4.w, 0.f);
    *(float4*)&out[(size_t)n * HD + lane * 4] = r;
}

// C[n,OUT] = X[n,128] @ W[128,OUT] + Bias, optionally fused LayerNorm(128)+ReLU.
// 128x128 tile, 256 threads, FFMA2 inner loop, double-buffered smem stages. (R10)
__global__ __launch_bounds__(256, 2)
void k_gemm(const float* __restrict__ X, const float* __restrict__ W,
            const float* __restrict__ Bias, const float* __restrict__ lng,
            const float* __restrict__ lnb, float* __restrict__ C,
            int n, int OUT, int do_ln) {
    __shared__ float xs[2][32][132];
    __shared__ float ws[2][32][132];
    int row0 = blockIdx.x * 128, col0 = blockIdx.y * 128;
    int tid = threadIdx.x;
    int tx = tid & 15, ty = tid >> 4;

    int xm = tid >> 1, xk = (tid & 1) * 16;
    int wk0 = tid >> 5, wc = (tid & 31) * 4;

    float4 xr[4], wr[4];
    int buf = 0;

    {
        int kb = 0;
#pragma unroll
        for (int q = 0; q < 4; ++q) {
            int row = row0 + xm;
            xr[q] = (row < n) ? *(const float4*)&X[(size_t)row * 128 + kb + xk + q * 4]
                              : make_float4(0.f, 0.f, 0.f, 0.f);
        }
#pragma unroll
        for (int q = 0; q < 4; ++q)
            wr[q] = *(const float4*)&W[(size_t)(kb + wk0 + q * 8) * OUT + col0 + wc];
#pragma unroll
        for (int q = 0; q < 4; ++q) {
            xs[0][xk + q * 4 + 0][xm] = xr[q].x;
            xs[0][xk + q * 4 + 1][xm] = xr[q].y;
            xs[0][xk + q * 4 + 2][xm] = xr[q].z;
            xs[0][xk + q * 4 + 3][xm] = xr[q].w;
            *(float4*)&ws[0][wk0 + q * 8][wc] = wr[q];
        }
    }
    __syncthreads();

    u64 acc2[8][4] = {};
#pragma unroll
    for (int kb = 0; kb < 128; kb += 32) {
        if (kb + 32 < 128) {
            int kn = kb + 32;
#pragma unroll
            for (int q = 0; q < 4; ++q) {
                int row = row0 + xm;
                xr[q] = (row < n) ? *(const float4*)&X[(size_t)row * 128 + kn + xk + q * 4]
                                  : make_float4(0.f, 0.f, 0.f, 0.f);
            }
#pragma unroll
            for (int q = 0; q < 4; ++q)
                wr[q] = *(const float4*)&W[(size_t)(kn + wk0 + q * 8) * OUT + col0 + wc];
        }
#pragma unroll
        for (int k = 0; k < 32; ++k) {
            float4 a0 = *(const float4*)&xs[buf][k][ty * 4];
            float4 a1 = *(const float4*)&xs[buf][k][64 + ty * 4];
            const u64* bp0 = (const u64*)&ws[buf][k][tx * 4];
            const u64* bp1 = (const u64*)&ws[buf][k][64 + tx * 4];
            u64 b01 = bp0[0], b23 = bp0[1];
            u64 b45 = bp1[0], b67 = bp1[1];
            float av[8] = {a0.x, a0.y, a0.z, a0.w, a1.x, a1.y, a1.z, a1.w};
#pragma unroll
            for (int i = 0; i < 8; ++i) {
                u64 aa = pack2(av[i], av[i]);
                acc2[i][0] = fma2(aa, b01, acc2[i][0]);
                acc2[i][1] = fma2(aa, b23, acc2[i][1]);
                acc2[i][2] = fma2(aa, b45, acc2[i][2]);
                acc2[i][3] = fma2(aa, b67, acc2[i][3]);
            }
        }
        if (kb + 32 < 128) {
            int nb = buf ^ 1;
#pragma unroll
            for (int q = 0; q < 4; ++q) {
                xs[nb][xk + q * 4 + 0][xm] = xr[q].x;
                xs[nb][xk + q * 4 + 1][xm] = xr[q].y;
                xs[nb][xk + q * 4 + 2][xm] = xr[q].z;
                xs[nb][xk + q * 4 + 3][xm] = xr[q].w;
                *(float4*)&ws[nb][wk0 + q * 8][wc] = wr[q];
            }
            __syncthreads();
            buf = nb;
        }
    }

    float acc[8][8];
#pragma unroll
    for (int i = 0; i < 8; ++i)
#pragma unroll
        for (int q = 0; q < 4; ++q)
            unpack2(acc2[i][q], acc[i][q * 2], acc[i][q * 2 + 1]);

    float pb[8];
#pragma unroll
    for (int j = 0; j < 8; ++j) {
        int col = col0 + (j < 4 ? tx * 4 + j : 64 + tx * 4 + j - 4);
        pb[j] = Bias[col];
    }
#pragma unroll
    for (int i = 0; i < 8; ++i)
#pragma unroll
        for (int j = 0; j < 8; ++j) acc[i][j] += pb[j];

    if (do_ln) {
        float gv[8], b2[8];
#pragma unroll
        for (int j = 0; j < 8; ++j) {
            int col = (j < 4 ? tx * 4 + j : 64 + tx * 4 + j - 4);
            gv[j] = lng[col]; b2[j] = lnb[col];
        }
#pragma unroll
        for (int i = 0; i < 8; ++i) {
            float s = 0.f;
#pragma unroll
            for (int j = 0; j < 8; ++j) s += acc[i][j];
#pragma unroll
            for (int o = 1; o < 16; o <<= 1) s += __shfl_xor_sync(0xffffffffu, s, o);
            float mu = s * (1.f / 128.f);
            float q = 0.f;
#pragma unroll
            for (int j = 0; j < 8; ++j) { float d = acc[i][j] - mu; q += d * d; }
#pragma unroll
            for (int o = 1; o < 16; o <<= 1) q += __shfl_xor_sync(0xffffffffu, q, o);
            float rs = rsqrtf(q * (1.f / 128.f) + LN_EPS);
#pragma unroll
            for (int j = 0; j < 8; ++j)
                acc[i][j] = fmaxf((acc[i][j] - mu) * rs * gv[j] + b2[j], 0.f);
        }
    }
#pragma unroll
    for (int i = 0; i < 8; ++i) {
        int row = row0 + (i < 4 ? ty * 4 + i : 64 + ty * 4 + i - 4);
        if (row < n) {
            float4 o0 = make_float4(acc[i][0], acc[i][1], acc[i][2], acc[i][3]);
            float4 o1 = make_float4(acc[i][4], acc[i][5], acc[i][6], acc[i][7]);
            *(float4*)&C[(size_t)row * OUT + col0 + tx * 4]      = o0;
            *(float4*)&C[(size_t)row * OUT + col0 + 64 + tx * 4] = o1;
        }
    }
}

// ---------------- fused per-destination prop kernel ----------------
// Warp per dst node; single-pass online-softmax GAT + label prop, f32x2 math.
// H16: label gathers read from a fp16 copy of yin (halves L2 traffic; all
// label values are non-negative so the fp16 rounding error stays <= 4.9e-4
// relative, with no cancellation). WR16: also emit a fp16 copy of yout.
template<int H16, int WR16>
__global__ void k_prop(const float* __restrict__ f, const float* __restrict__ x,
                       const float* __restrict__ yin, const __half* __restrict__ yin16,
                       const float* __restrict__ attn,
                       const int* __restrict__ offp, const int* __restrict__ sp,
                       const int* __restrict__ offs2, const int* __restrict__ ss,
                       const void* __restrict__ flag,
                       float* __restrict__ hout, float* __restrict__ yout,
                       __half* __restrict__ yout16) {
    int v = blockIdx.x * 8 + (threadIdx.x >> 5);
    if (v >= NN) return;
    int lane = threadIdx.x & 31;

    float4 at = *(const float4*)&attn[lane * 4];
    u64 at06_0 = pack2(0.6f * at.x, 0.6f * at.y);
    u64 at06_1 = pack2(0.6f * at.z, 0.6f * at.w);
    u64 at04_0 = pack2(0.4f * at.x, 0.4f * at.y);
    u64 at04_1 = pack2(0.4f * at.z, 0.4f * at.w);
    ulonglong2 fv2 = *(const ulonglong2*)&f[(size_t)v * HD + lane * 4];

    float4 tf  = make_float4(0.f, 0.f, 0.f, 0.f);
    float4 ty0 = make_float4(0.f, 0.f, 0.f, 0.f);
    float4 ty1 = make_float4(0.f, 0.f, 0.f, 0.f);

#pragma unroll
    for (int rel = 0; rel < 2; ++rel) {
        const int* off  = rel ? offs2 : offp;
        const int* ssrc = rel ? ss    : sp;
        int lo = off[v], hi = off[v + 1];

        float m   = -__int_as_float(0x7f800000);
        float den = 0.f;
        u64 af0 = 0, af1 = 0, a00 = 0, a01 = 0, a10 = 0, a11 = 0;

        for (int base = lo; base < hi; base += 32) {
            int j = base + lane;
            int myu = (j < hi) ? __ldg(&ssrc[j]) : 0;
            int cnt = min(32, hi - base);
#pragma unroll 2
            for (int t = 0; t < cnt; ++t) {
                int u = __shfl_sync(0xffffffffu, myu, t);
                ulonglong2 fu = *(const ulonglong2*)&f[(size_t)u * HD + lane * 4];
                u64 y0x, y0y, y1x, y1y;
                if (H16) {
                    // 4+4 halves per half-row chunk (8B loads)
                    uint2 ha = *(const uint2*)&yin16[(size_t)u * OD + lane * 4];
                    uint2 hb = *(const uint2*)&yin16[(size_t)u * OD + 128 + lane * 4];
                    float2 p0 = __half22float2(*(const __half2*)&ha.x);
                    float2 p1 = __half22float2(*(const __half2*)&ha.y);
                    float2 p2 = __half22float2(*(const __half2*)&hb.x);
                    float2 p3 = __half22float2(*(const __half2*)&hb.y);
                    y0x = pack2(p0.x, p0.y); y0y = pack2(p1.x, p1.y);
                    y1x = pack2(p2.x, p2.y); y1y = pack2(p3.x, p3.y);
                } else {
                    ulonglong2 y0 = *(const ulonglong2*)&yin[(size_t)u * OD + lane * 4];
                    ulonglong2 y1 = *(const ulonglong2*)&yin[(size_t)u * OD + 128 + lane * 4];
                    y0x = y0.x; y0y = y0.y; y1x = y1.x; y1y = y1.y;
                }
                u64 z0 = add2(fu.x, fv2.x);
                u64 z1 = add2(fu.y, fv2.y);
                u64 p2v = mul2(z0, at06_0);
                p2v = fma2(abs2(z0), at04_0, p2v);
                p2v = fma2(z1, at06_1, p2v);
                p2v = fma2(abs2(z1), at04_1, p2v);
                float px, py;
                unpack2(p2v, px, py);
                float p = px + py;
#pragma unroll
                for (int o = 16; o; o >>= 1) p += __shfl_xor_sync(0xffffffffu, p, o);
                if (p > m) {
                    float r = __expf(m - p);   // 0 on first edge (m = -inf)
                    den *= r;
                    u64 r2 = pack2(r, r);
                    af0 = mul2(af0, r2); af1 = mul2(af1, r2);
                    a00 = mul2(a00, r2); a01 = mul2(a01, r2);
                    a10 = mul2(a10, r2); a11 = mul2(a11, r2);
                    m = p;
                }
                float w = __expf(p - m);
                den += w;
                u64 w2 = pack2(w, w);
                af0 = fma2(fu.x, w2, af0); af1 = fma2(fu.y, w2, af1);
                a00 = fma2(y0x, w2, a00); a01 = fma2(y0y, w2, a01);
                a10 = fma2(y1x, w2, a10); a11 = fma2(y1y, w2, a11);
            }
        }
        float rden = (den > 0.f) ? 1.f / den : 0.f;
        float e0, e1;
        unpack2(af0, e0, e1); tf.x  = fmaf(e0, rden, tf.x);  tf.y  = fmaf(e1, rden, tf.y);
        unpack2(af1, e0, e1); tf.z  = fmaf(e0, rden, tf.z);  tf.w  = fmaf(e1, rden, tf.w);
        unpack2(a00, e0, e1); ty0.x = fmaf(e0, rden, ty0.x); ty0.y = fmaf(e1, rden, ty0.y);
        unpack2(a01, e0, e1); ty0.z = fmaf(e0, rden, ty0.z); ty0.w = fmaf(e1, rden, ty0.w);
        unpack2(a10, e0, e1); ty1.x = fmaf(e0, rden, ty1.x); ty1.y = fmaf(e1, rden, ty1.y);
        unpack2(a11, e0, e1); ty1.z = fmaf(e0, rden, ty1.z); ty1.w = fmaf(e1, rden, ty1.w);
    }

    // h epilogue: elu(agg_p + agg_s + 2*x)
    float4 xv = *(const float4*)&x[(size_t)v * HD + lane * 4];
    float4 h;
    h.x = tf.x + 2.f * xv.x; h.x = h.x > 0.f ? h.x : expm1f(h.x);
    h.y = tf.y + 2.f * xv.y; h.y = h.y > 0.f ? h.y : expm1f(h.y);
    h.z = tf.z + 2.f * xv.z; h.z = h.z > 0.f ? h.z : expm1f(h.z);
    h.w = tf.w + 2.f * xv.w; h.w = h.w > 0.f ? h.w : expm1f(h.w);
    *(float4*)&hout[(size_t)v * HD + lane * 4] = h;

    // y epilogue: normalize or copy per flag
    float q = ty0.x * ty0.x + ty0.y * ty0.y + ty0.z * ty0.z + ty0.w * ty0.w
            + ty1.x * ty1.x + ty1.y * ty1.y + ty1.z * ty1.z + ty1.w * ty1.w;
#pragma unroll
    for (int o = 16; o; o >>= 1) q += __shfl_xor_sync(0xffffffffu, q, o);
    float inv = 1.f / fmaxf(sqrtf(q), 1e-12f);
    bool fl;
    if (g_flagIsInt) fl = ((const int*)flag)[v] != 0;
    else             fl = ((const unsigned char*)flag)[v] != 0;
    size_t base = (size_t)v * OD + lane * 4;
    float4 r0, r1;
    if (fl) {
        r0 = *(const float4*)&yin[base];
        r1 = *(const float4*)&yin[base + 128];
    } else {
        r0 = make_float4(ty0.x * inv, ty0.y * inv, ty0.z * inv, ty0.w * inv);
        r1 = make_float4(ty1.x * inv, ty1.y * inv, ty1.z * inv, ty1.w * inv);
    }
    *(float4*)&yout[base]       = r0;
    *(float4*)&yout[base + 128] = r1;

    if (WR16) {
        __half2 h0 = __float22half2_rn(make_float2(r0.x, r0.y));
        __half2 h1 = __float22half2_rn(make_float2(r0.z, r0.w));
        __half2 h2 = __float22half2_rn(make_float2(r1.x, r1.y));
        __half2 h3 = __float22half2_rn(make_float2(r1.z, r1.w));
        uint2 pa, pb2;
        pa.x  = *(unsigned*)&h0; pa.y  = *(unsigned*)&h1;
        pb2.x = *(unsigned*)&h2; pb2.y = *(unsigned*)&h3;
        *(uint2*)&yout16[base]       = pa;
        *(uint2*)&yout16[base + 128] = pb2;
    }
}

// ---------------- host orchestration ----------------
extern "C" void kernel_launch(void* const* d_in, const int* in_sizes, int n_in,
                              void* d_out, int out_size) {
    const int*   emb_indices = (const int*)  d_in[0];
    const int*   emb_offsets = (const int*)  d_in[1];
    const float* emb_weights = (const float*)d_in[2];
    const float* y           = (const float*)d_in[3];
    const void*  flag        = d_in[4];
    const int* src_p1 = (const int*)d_in[5];
    const int* dst_p1 = (const int*)d_in[6];
    const int* src_s1 = (const int*)d_in[7];
    const int* dst_s1 = (const int*)d_in[8];
    const int* src_p2 = (const int*)d_in[9];
    const int* dst_p2 = (const int*)d_in[10];
    const int* src_s2 = (const int*)d_in[11];
    const int* dst_s2 = (const int*)d_in[12];
    const float* embed_W = (const float*)d_in[13];
    const float* embed_b = (const float*)d_in[14];
    const float* mlp_W1  = (const float*)d_in[15];
    const float* mlp_b1  = (const float*)d_in[16];
    const float* ln1_g   = (const float*)d_in[17];
    const float* ln1_b   = (const float*)d_in[18];
    const float* mlp_W2  = (const float*)d_in[19];
    const float* mlp_b2  = (const float*)d_in[20];
    const float* ln2_g   = (const float*)d_in[21];
    const float* ln2_b   = (const float*)d_in[22];
    const float* Wsrc1   = (const float*)d_in[23];
    const float* bsrc1   = (const float*)d_in[24];
    const float* attn1   = (const float*)d_in[25];
    const float* Wsrc2   = (const float*)d_in[26];
    const float* bsrc2   = (const float*)d_in[27];
    const float* attn2   = (const float*)d_in[28];
    const float* out_W   = (const float*)d_in[29];
    const float* out_b   = (const float*)d_in[30];

    float *hA, *hB, *f, *yA;
    __half* yA16;
    int *off, *ssrc, *cnt, *cur;
    cudaGetSymbolAddress((void**)&hA,   g_hA);
    cudaGetSymbolAddress((void**)&hB,   g_hB);
    cudaGetSymbolAddress((void**)&f,    g_f);
    cudaGetSymbolAddress((void**)&yA,   g_yA);
    cudaGetSymbolAddress((void**)&yA16, g_yA16);
    cudaGetSymbolAddress((void**)&off,  g_off);
    cudaGetSymbolAddress((void**)&ssrc, g_ssrc);
    cudaGetSymbolAddress((void**)&cnt,  g_cnt);
    cudaGetSymbolAddress((void**)&cur,  g_cur);

    float* logits = (float*)d_out;
    float* yh_out = (float*)d_out + (size_t)NN * OD;

    // Side stream for the CSR build (independent of embed+MLP); capture-legal
    // fork/join via events.
    cudaStream_t s2;
    cudaEvent_t ev0, ev1;
    cudaStreamCreateWithFlags(&s2, cudaStreamNonBlocking);
    cudaEventCreateWithFlags(&ev0, cudaEventDisableTiming);
    cudaEventCreateWithFlags(&ev1, cudaEventDisableTiming);

    cudaEventRecord(ev0, 0);

    // ---- main branch: EmbeddingBag + MLP (LN fused) + f-GEMM for prop1 ----
    k_embed<<<(NN + 7) / 8, 256>>>(emb_indices, emb_offsets, emb_weights, embed_W, embed_b, hA);
    dim3 g1((NN + 127) / 128, 1);
    k_gemm<<<g1, 256>>>(hA, mlp_W1, mlp_b1, ln1_g, ln1_b, hB, NN, 128, 1);
    k_gemm<<<g1, 256>>>(hB, mlp_W2, mlp_b2, ln2_g, ln2_b, hA, NN, 128, 1);
    k_gemm<<<g1, 256>>>(hA, Wsrc1, bsrc1, nullptr, nullptr, f, NN, 128, 0);

    // ---- side branch: flag detect + CSR sorts for the 4 relations ----
    cudaStreamWaitEvent(s2, ev0, 0);
    k_detect_flag<<<1, 256, 0, s2>>>((const unsigned char*)flag);
    cudaMemsetAsync(cnt, 0, sizeof(int) * 4 * NN, s2);
    dim3 ge((NE + 255) / 256, 4);
    k_hist4<<<ge, 256, 0, s2>>>(dst_p1, dst_s1, dst_p2, dst_s2, cnt);
    k_scan4<<<4, 1024, 0, s2>>>(cnt, off, cur);
    k_scatter4<<<ge, 256, 0, s2>>>(src_p1, dst_p1, src_s1, dst_s1,
                                   src_p2, dst_p2, src_s2, dst_s2, cur, ssrc);
    cudaEventRecord(ev1, s2);

    // ---- join, then props ----
    cudaStreamWaitEvent(0, ev1, 0);
    // prop 1: full fp32, also emits yA16 (fp16 copy of yA) for prop2's gather
    k_prop<0, 1><<<(NN + 7) / 8, 256>>>(f, hA, y, nullptr, attn1,
                                        off + 0 * (NN + 1), ssrc + 0 * NE,
                                        off + 1 * (NN + 1), ssrc + 1 * NE,
                                        flag, hB, yA, yA16);

    k_gemm<<<g1, 256>>>(hB, Wsrc2, bsrc2, nullptr, nullptr, f, NN, 128, 0);
    // prop 2: gathers labels from fp16 yA16 (half the L2 bytes); epilogue
    // flagged-copy still reads exact fp32 yA.
    k_prop<1, 0><<<(NN + 7) / 8, 256>>>(f, hB, yA, yA16, attn2,
                                        off + 2 * (NN + 1), ssrc + 2 * NE,
                                        off + 3 * (NN + 1), ssrc + 3 * NE,
                                        flag, hA, yh_out, nullptr);

    // ---- logits = h @ out_W + out_b ----
    dim3 g2((NN + 127) / 128, 2);
    k_gemm<<<g2, 256>>>(hA, out_W, out_b, nullptr, nullptr, logits, NN, 256, 0);
}

// round 14
// speedup vs baseline: 1.1816x; 1.1274x over previous
#include <cuda_runtime.h>
#include <cuda_fp16.h>
#include <math.h>

#define NN 50000
#define HD 128
#define OD 256
#define NE 800000
#define LN_EPS 1e-5f

typedef unsigned long long u64;

// ---------------- scratch (static device globals; no allocation) ----------------
__device__ float  g_hA[NN * HD];
__device__ float  g_hB[NN * HD];
__device__ float  g_f [NN * HD];
__device__ float  g_yA [NN * OD];
__device__ __half g_y16 [NN * OD];
__device__ __half g_yA16[NN * OD];
__device__ int    g_off [4][NN + 1];
__device__ int    g_ssrc[4][NE];
__device__ int    g_cnt[4][NN];
__device__ int    g_cur[4][NN];
__device__ int    g_flagIsInt;

// ---------------- helpers ----------------
__device__ __forceinline__ u64 pack2(float lo, float hi) {
    u64 r;
    asm("mov.b64 %0, {%1, %2};" : "=l"(r) : "f"(lo), "f"(hi));
    return r;
}
__device__ __forceinline__ void unpack2(u64 v, float& lo, float& hi) {
    asm("mov.b64 {%0, %1}, %2;" : "=f"(lo), "=f"(hi) : "l"(v));
}
__device__ __forceinline__ u64 fma2(u64 a, u64 b, u64 c) {
    u64 d;
    asm("fma.rn.f32x2 %0, %1, %2, %3;" : "=l"(d) : "l"(a), "l"(b), "l"(c));
    return d;
}
__device__ __forceinline__ u64 mul2(u64 a, u64 b) {
    u64 d;
    asm("mul.rn.f32x2 %0, %1, %2;" : "=l"(d) : "l"(a), "l"(b));
    return d;
}
__device__ __forceinline__ u64 add2(u64 a, u64 b) {
    u64 d;
    asm("add.rn.f32x2 %0, %1, %2;" : "=l"(d) : "l"(a), "l"(b));
    return d;
}
__device__ __forceinline__ u64 abs2(u64 a) {
    return a & 0x7FFFFFFF7FFFFFFFULL;
}

// ---------------- kernels ----------------

// Detect flag buffer layout: int32 (bytes 1..3 of each word are 0) vs uint8.
__global__ void k_detect_flag(const unsigned char* __restrict__ flag) {
    __shared__ int cnt;
    if (threadIdx.x == 0) cnt = 0;
    __syncthreads();
    int local = 0;
    for (int i = threadIdx.x; i < 4000; i += 256)
        if ((i & 3) != 0 && flag[i] != 0) local = 1;
    if (local) atomicOr(&cnt, 1);
    __syncthreads();
    if (threadIdx.x == 0) g_flagIsInt = (cnt == 0) ? 1 : 0;
}

// fp32 -> fp16 conversion for the label matrix (vectorized 4-at-a-time).
__global__ void k_y2h(const float* __restrict__ in, __half* __restrict__ out) {
    int i = blockIdx.x * 256 + threadIdx.x;
    if (i < NN * OD / 4) {
        float4 v = *(const float4*)&in[i * 4];
        __half2 h0 = __float22half2_rn(make_float2(v.x, v.y));
        __half2 h1 = __float22half2_rn(make_float2(v.z, v.w));
        uint2 p;
        p.x = *(unsigned*)&h0; p.y = *(unsigned*)&h1;
        *(uint2*)&out[i * 4] = p;
    }
}

// -------- counting sort by dst (all 4 relations in one grid via blockIdx.y) --------
__global__ void k_hist4(const int* __restrict__ d0, const int* __restrict__ d1,
                        const int* __restrict__ d2, const int* __restrict__ d3,
                        int* __restrict__ cnt) {
    int e = blockIdx.x * 256 + threadIdx.x;
    int r = blockIdx.y;
    const int* dst = r == 0 ? d0 : r == 1 ? d1 : r == 2 ? d2 : d3;
    if (e < NE) atomicAdd(&cnt[r * NN + dst[e]], 1);
}

// 4 blocks, one relation each: exclusive scan -> offs[NN+1], cur[NN]
__global__ void k_scan4(const int* __restrict__ cntAll, int* __restrict__ offsAll,
                        int* __restrict__ curAll) {
    __shared__ int part[1024];
    const int CH = (NN + 1023) / 1024;
    int r = blockIdx.x;
    const int* cnt = cntAll + r * NN;
    int* offs = offsAll + r * (NN + 1);
    int* cur  = curAll  + r * NN;
    int t = threadIdx.x;
    int lo = t * CH, hi = min(lo + CH, NN);
    int s = 0;
    for (int i = lo; i < hi; ++i) s += cnt[i];
    part[t] = s;
    __syncthreads();
    for (int o = 1; o < 1024; o <<= 1) {
        int v = (t >= o) ? part[t - o] : 0;
        __syncthreads();
        part[t] += v;
        __syncthreads();
    }
    int base = (t == 0) ? 0 : part[t - 1];
    for (int i = lo; i < hi; ++i) {
        offs[i] = base;
        cur[i]  = base;
        base += cnt[i];
    }
    if (t == 1023) offs[NN] = base;
}

__global__ void k_scatter4(const int* __restrict__ s0, const int* __restrict__ d0,
                           const int* __restrict__ s1, const int* __restrict__ d1,
                           const int* __restrict__ s2, const int* __restrict__ d2,
                           const int* __restrict__ s3, const int* __restrict__ d3,
                           int* __restrict__ cur, int* __restrict__ ssrc) {
    int e = blockIdx.x * 256 + threadIdx.x;
    int r = blockIdx.y;
    const int* src = r == 0 ? s0 : r == 1 ? s1 : r == 2 ? s2 : s3;
    const int* dst = r == 0 ? d0 : r == 1 ? d1 : r == 2 ? d2 : d3;
    if (e < NE) {
        int v = dst[e];
        int pos = atomicAdd(&cur[r * NN + v], 1);
        ssrc[r * NE + pos] = src[e];
    }
}

// EmbeddingBag(sum, per_sample_weights) + bias + relu. Warp per node.
__global__ void k_embed(const int* __restrict__ idx, const int* __restrict__ offs,
                        const float* __restrict__ wts, const float* __restrict__ table,
                        const float* __restrict__ bias, float* __restrict__ out) {
    int n = blockIdx.x * 8 + (threadIdx.x >> 5);
    if (n >= NN) return;
    int lane = threadIdx.x & 31;
    int s = offs[n], e = offs[n + 1];
    float4 acc = make_float4(0.f, 0.f, 0.f, 0.f);
    for (int base = s; base < e; base += 32) {
        int j = base + lane;
        int id = (j < e) ? idx[j] : 0;
        float w = (j < e) ? wts[j] : 0.f;
        int cnt = min(32, e - base);
#pragma unroll 2
        for (int t = 0; t < cnt; ++t) {
            int   uj = __shfl_sync(0xffffffffu, id, t);
            float wj = __shfl_sync(0xffffffffu, w,  t);
            float4 tv = *(const float4*)&table[(size_t)uj * HD + lane * 4];
            acc.x = fmaf(tv.x, wj, acc.x);
            acc.y = fmaf(tv.y, wj, acc.y);
            acc.z = fmaf(tv.z, wj, acc.z);
            acc.w = fmaf(tv.w, wj, acc.w);
        }
    }
    float4 b4 = *(const float4*)&bias[lane * 4];
    float4 r;
    r.x = fmaxf(acc.x + b4.x, 0.f);
    r.y = fmaxf(acc.y + b4.y, 0.f);
    r.z = fmaxf(acc.z + b4.z, 0.f);
    r.w = fmaxf(acc.w + b4.w, 0.f);
    *(float4*)&out[(size_t)n * HD + lane * 4] = r;
}

// C[n,OUT] = X[n,128] @ W[128,OUT] + Bias, optionally fused LayerNorm(128)+ReLU.
// 128x128 tile, 256 threads, FFMA2 inner loop, double-buffered smem stages. (R10)
__global__ __launch_bounds__(256, 2)
void k_gemm(const float* __restrict__ X, const float* __restrict__ W,
            const float* __restrict__ Bias, const float* __restrict__ lng,
            const float* __restrict__ lnb, float* __restrict__ C,
            int n, int OUT, int do_ln) {
    __shared__ float xs[2][32][132];
    __shared__ float ws[2][32][132];
    int row0 = blockIdx.x * 128, col0 = blockIdx.y * 128;
    int tid = threadIdx.x;
    int tx = tid & 15, ty = tid >> 4;

    int xm = tid >> 1, xk = (tid & 1) * 16;
    int wk0 = tid >> 5, wc = (tid & 31) * 4;

    float4 xr[4], wr[4];
    int buf = 0;

    {
        int kb = 0;
#pragma unroll
        for (int q = 0; q < 4; ++q) {
            int row = row0 + xm;
            xr[q] = (row < n) ? *(const float4*)&X[(size_t)row * 128 + kb + xk + q * 4]
                              : make_float4(0.f, 0.f, 0.f, 0.f);
        }
#pragma unroll
        for (int q = 0; q < 4; ++q)
            wr[q] = *(const float4*)&W[(size_t)(kb + wk0 + q * 8) * OUT + col0 + wc];
#pragma unroll
        for (int q = 0; q < 4; ++q) {
            xs[0][xk + q * 4 + 0][xm] = xr[q].x;
            xs[0][xk + q * 4 + 1][xm] = xr[q].y;
            xs[0][xk + q * 4 + 2][xm] = xr[q].z;
            xs[0][xk + q * 4 + 3][xm] = xr[q].w;
            *(float4*)&ws[0][wk0 + q * 8][wc] = wr[q];
        }
    }
    __syncthreads();

    u64 acc2[8][4] = {};
#pragma unroll
    for (int kb = 0; kb < 128; kb += 32) {
        if (kb + 32 < 128) {
            int kn = kb + 32;
#pragma unroll
            for (int q = 0; q < 4; ++q) {
                int row = row0 + xm;
                xr[q] = (row < n) ? *(const float4*)&X[(size_t)row * 128 + kn + xk + q * 4]
                                  : make_float4(0.f, 0.f, 0.f, 0.f);
            }
#pragma unroll
            for (int q = 0; q < 4; ++q)
                wr[q] = *(const float4*)&W[(size_t)(kn + wk0 + q * 8) * OUT + col0 + wc];
        }
#pragma unroll
        for (int k = 0; k < 32; ++k) {
            float4 a0 = *(const float4*)&xs[buf][k][ty * 4];
            float4 a1 = *(const float4*)&xs[buf][k][64 + ty * 4];
            const u64* bp0 = (const u64*)&ws[buf][k][tx * 4];
            const u64* bp1 = (const u64*)&ws[buf][k][64 + tx * 4];
            u64 b01 = bp0[0], b23 = bp0[1];
            u64 b45 = bp1[0], b67 = bp1[1];
            float av[8] = {a0.x, a0.y, a0.z, a0.w, a1.x, a1.y, a1.z, a1.w};
#pragma unroll
            for (int i = 0; i < 8; ++i) {
                u64 aa = pack2(av[i], av[i]);
                acc2[i][0] = fma2(aa, b01, acc2[i][0]);
                acc2[i][1] = fma2(aa, b23, acc2[i][1]);
                acc2[i][2] = fma2(aa, b45, acc2[i][2]);
                acc2[i][3] = fma2(aa, b67, acc2[i][3]);
            }
        }
        if (kb + 32 < 128) {
            int nb = buf ^ 1;
#pragma unroll
            for (int q = 0; q < 4; ++q) {
                xs[nb][xk + q * 4 + 0][xm] = xr[q].x;
                xs[nb][xk + q * 4 + 1][xm] = xr[q].y;
                xs[nb][xk + q * 4 + 2][xm] = xr[q].z;
                xs[nb][xk + q * 4 + 3][xm] = xr[q].w;
                *(float4*)&ws[nb][wk0 + q * 8][wc] = wr[q];
            }
            __syncthreads();
            buf = nb;
        }
    }

    float acc[8][8];
#pragma unroll
    for (int i = 0; i < 8; ++i)
#pragma unroll
        for (int q = 0; q < 4; ++q)
            unpack2(acc2[i][q], acc[i][q * 2], acc[i][q * 2 + 1]);

    float pb[8];
#pragma unroll
    for (int j = 0; j < 8; ++j) {
        int col = col0 + (j < 4 ? tx * 4 + j : 64 + tx * 4 + j - 4);
        pb[j] = Bias[col];
    }
#pragma unroll
    for (int i = 0; i < 8; ++i)
#pragma unroll
        for (int j = 0; j < 8; ++j) acc[i][j] += pb[j];

    if (do_ln) {
        float gv[8], b2[8];
#pragma unroll
        for (int j = 0; j < 8; ++j) {
            int col = (j < 4 ? tx * 4 + j : 64 + tx * 4 + j - 4);
            gv[j] = lng[col]; b2[j] = lnb[col];
        }
#pragma unroll
        for (int i = 0; i < 8; ++i) {
            float s = 0.f;
#pragma unroll
            for (int j = 0; j < 8; ++j) s += acc[i][j];
#pragma unroll
            for (int o = 1; o < 16; o <<= 1) s += __shfl_xor_sync(0xffffffffu, s, o);
            float mu = s * (1.f / 128.f);
            float q = 0.f;
#pragma unroll
            for (int j = 0; j < 8; ++j) { float d = acc[i][j] - mu; q += d * d; }
#pragma unroll
            for (int o = 1; o < 16; o <<= 1) q += __shfl_xor_sync(0xffffffffu, q, o);
            float rs = rsqrtf(q * (1.f / 128.f) + LN_EPS);
#pragma unroll
            for (int j = 0; j < 8; ++j)
                acc[i][j] = fmaxf((acc[i][j] - mu) * rs * gv[j] + b2[j], 0.f);
        }
    }
#pragma unroll
    for (int i = 0; i < 8; ++i) {
        int row = row0 + (i < 4 ? ty * 4 + i : 64 + ty * 4 + i - 4);
        if (row < n) {
            float4 o0 = make_float4(acc[i][0], acc[i][1], acc[i][2], acc[i][3]);
            float4 o1 = make_float4(acc[i][4], acc[i][5], acc[i][6], acc[i][7]);
            *(float4*)&C[(size_t)row * OUT + col0 + tx * 4]      = o0;
            *(float4*)&C[(size_t)row * OUT + col0 + 64 + tx * 4] = o1;
        }
    }
}

// ---------------- fused per-destination prop kernel ----------------
// Warp per dst node; single-pass online-softmax GAT + label prop, f32x2 math.
// Label gathers read fp16 (halves label L2 traffic; labels non-negative so
// rounding error is benign — measured 9.4e-6 end-to-end). WR16 emits a fp16
// copy of yout for the next prop. __launch_bounds__(256,3) raises occupancy
// to 6 warps/SMSP to hide the gather + shfl-chain latency.
template<int WR16>
__global__ __launch_bounds__(256, 3)
void k_prop(const float* __restrict__ f, const float* __restrict__ x,
            const float* __restrict__ yin, const __half* __restrict__ yin16,
            const float* __restrict__ attn,
            const int* __restrict__ offp, const int* __restrict__ sp,
            const int* __restrict__ offs2, const int* __restrict__ ss,
            const void* __restrict__ flag,
            float* __restrict__ hout, float* __restrict__ yout,
            __half* __restrict__ yout16) {
    int v = blockIdx.x * 8 + (threadIdx.x >> 5);
    if (v >= NN) return;
    int lane = threadIdx.x & 31;

    float4 at = *(const float4*)&attn[lane * 4];
    u64 at06_0 = pack2(0.6f * at.x, 0.6f * at.y);
    u64 at06_1 = pack2(0.6f * at.z, 0.6f * at.w);
    u64 at04_0 = pack2(0.4f * at.x, 0.4f * at.y);
    u64 at04_1 = pack2(0.4f * at.z, 0.4f * at.w);
    ulonglong2 fv2 = *(const ulonglong2*)&f[(size_t)v * HD + lane * 4];

    float4 tf  = make_float4(0.f, 0.f, 0.f, 0.f);
    float4 ty0 = make_float4(0.f, 0.f, 0.f, 0.f);
    float4 ty1 = make_float4(0.f, 0.f, 0.f, 0.f);

#pragma unroll
    for (int rel = 0; rel < 2; ++rel) {
        const int* off  = rel ? offs2 : offp;
        const int* ssrc = rel ? ss    : sp;
        int lo = off[v], hi = off[v + 1];

        float m   = -__int_as_float(0x7f800000);
        float den = 0.f;
        u64 af0 = 0, af1 = 0, a00 = 0, a01 = 0, a10 = 0, a11 = 0;

        for (int base = lo; base < hi; base += 32) {
            int j = base + lane;
            int myu = (j < hi) ? __ldg(&ssrc[j]) : 0;
            int cnt = min(32, hi - base);
#pragma unroll 2
            for (int t = 0; t < cnt; ++t) {
                int u = __shfl_sync(0xffffffffu, myu, t);
                ulonglong2 fu = *(const ulonglong2*)&f[(size_t)u * HD + lane * 4];
                // fp16 label gathers (8B per half-row chunk)
                uint2 ha = *(const uint2*)&yin16[(size_t)u * OD + lane * 4];
                uint2 hb = *(const uint2*)&yin16[(size_t)u * OD + 128 + lane * 4];
                float2 p0 = __half22float2(*(const __half2*)&ha.x);
                float2 p1 = __half22float2(*(const __half2*)&ha.y);
                float2 p2h = __half22float2(*(const __half2*)&hb.x);
                float2 p3 = __half22float2(*(const __half2*)&hb.y);
                u64 y0x = pack2(p0.x, p0.y), y0y = pack2(p1.x, p1.y);
                u64 y1x = pack2(p2h.x, p2h.y), y1y = pack2(p3.x, p3.y);

                u64 z0 = add2(fu.x, fv2.x);
                u64 z1 = add2(fu.y, fv2.y);
                u64 p2v = mul2(z0, at06_0);
                p2v = fma2(abs2(z0), at04_0, p2v);
                p2v = fma2(z1, at06_1, p2v);
                p2v = fma2(abs2(z1), at04_1, p2v);
                float px, py;
                unpack2(p2v, px, py);
                float p = px + py;
#pragma unroll
                for (int o = 16; o; o >>= 1) p += __shfl_xor_sync(0xffffffffu, p, o);
                if (p > m) {
                    float r = __expf(m - p);   // 0 on first edge (m = -inf)
                    den *= r;
                    u64 r2 = pack2(r, r);
                    af0 = mul2(af0, r2); af1 = mul2(af1, r2);
                    a00 = mul2(a00, r2); a01 = mul2(a01, r2);
                    a10 = mul2(a10, r2); a11 = mul2(a11, r2);
                    m = p;
                }
                float w = __expf(p - m);
                den += w;
                u64 w2 = pack2(w, w);
                af0 = fma2(fu.x, w2, af0); af1 = fma2(fu.y, w2, af1);
                a00 = fma2(y0x, w2, a00); a01 = fma2(y0y, w2, a01);
                a10 = fma2(y1x, w2, a10); a11 = fma2(y1y, w2, a11);
            }
        }
        float rden = (den > 0.f) ? 1.f / den : 0.f;
        float e0, e1;
        unpack2(af0, e0, e1); tf.x  = fmaf(e0, rden, tf.x);  tf.y  = fmaf(e1, rden, tf.y);
        unpack2(af1, e0, e1); tf.z  = fmaf(e0, rden, tf.z);  tf.w  = fmaf(e1, rden, tf.w);
        unpack2(a00, e0, e1); ty0.x = fmaf(e0, rden, ty0.x); ty0.y = fmaf(e1, rden, ty0.y);
        unpack2(a01, e0, e1); ty0.z = fmaf(e0, rden, ty0.z); ty0.w = fmaf(e1, rden, ty0.w);
        unpack2(a10, e0, e1); ty1.x = fmaf(e0, rden, ty1.x); ty1.y = fmaf(e1, rden, ty1.y);
        unpack2(a11, e0, e1); ty1.z = fmaf(e0, rden, ty1.z); ty1.w = fmaf(e1, rden, ty1.w);
    }

    // h epilogue: elu(agg_p + agg_s + 2*x)
    float4 xv = *(const float4*)&x[(size_t)v * HD + lane * 4];
    float4 h;
    h.x = tf.x + 2.f * xv.x; h.x = h.x > 0.f ? h.x : expm1f(h.x);
    h.y = tf.y + 2.f * xv.y; h.y = h.y > 0.f ? h.y : expm1f(h.y);
    h.z = tf.z + 2.f * xv.z; h.z = h.z > 0.f ? h.z : expm1f(h.z);
    h.w = tf.w + 2.f * xv.w; h.w = h.w > 0.f ? h.w : expm1f(h.w);
    *(float4*)&hout[(size_t)v * HD + lane * 4] = h;

    // y epilogue: normalize or copy per flag (flagged copy stays exact fp32)
    float q = ty0.x * ty0.x + ty0.y * ty0.y + ty0.z * ty0.z + ty0.w * ty0.w
            + ty1.x * ty1.x + ty1.y * ty1.y + ty1.z * ty1.z + ty1.w * ty1.w;
#pragma unroll
    for (int o = 16; o; o >>= 1) q += __shfl_xor_sync(0xffffffffu, q, o);
    float inv = 1.f / fmaxf(sqrtf(q), 1e-12f);
    bool fl;
    if (g_flagIsInt) fl = ((const int*)flag)[v] != 0;
    else             fl = ((const unsigned char*)flag)[v] != 0;
    size_t base = (size_t)v * OD + lane * 4;
    float4 r0, r1;
    if (fl) {
        r0 = *(const float4*)&yin[base];
        r1 = *(const float4*)&yin[base + 128];
    } else {
        r0 = make_float4(ty0.x * inv, ty0.y * inv, ty0.z * inv, ty0.w * inv);
        r1 = make_float4(ty1.x * inv, ty1.y * inv, ty1.z * inv, ty1.w * inv);
    }
    *(float4*)&yout[base]       = r0;
    *(float4*)&yout[base + 128] = r1;

    if (WR16) {
        __half2 h0 = __float22half2_rn(make_float2(r0.x, r0.y));
        __half2 h1 = __float22half2_rn(make_float2(r0.z, r0.w));
        __half2 h2 = __float22half2_rn(make_float2(r1.x, r1.y));
        __half2 h3 = __float22half2_rn(make_float2(r1.z, r1.w));
        uint2 pa, pb2;
        pa.x  = *(unsigned*)&h0; pa.y  = *(unsigned*)&h1;
        pb2.x = *(unsigned*)&h2; pb2.y = *(unsigned*)&h3;
        *(uint2*)&yout16[base]       = pa;
        *(uint2*)&yout16[base + 128] = pb2;
    }
}

// ---------------- host orchestration ----------------
extern "C" void kernel_launch(void* const* d_in, const int* in_sizes, int n_in,
                              void* d_out, int out_size) {
    const int*   emb_indices = (const int*)  d_in[0];
    const int*   emb_offsets = (const int*)  d_in[1];
    const float* emb_weights = (const float*)d_in[2];
    const float* y           = (const float*)d_in[3];
    const void*  flag        = d_in[4];
    const int* src_p1 = (const int*)d_in[5];
    const int* dst_p1 = (const int*)d_in[6];
    const int* src_s1 = (const int*)d_in[7];
    const int* dst_s1 = (const int*)d_in[8];
    const int* src_p2 = (const int*)d_in[9];
    const int* dst_p2 = (const int*)d_in[10];
    const int* src_s2 = (const int*)d_in[11];
    const int* dst_s2 = (const int*)d_in[12];
    const float* embed_W = (const float*)d_in[13];
    const float* embed_b = (const float*)d_in[14];
    const float* mlp_W1  = (const float*)d_in[15];
    const float* mlp_b1  = (const float*)d_in[16];
    const float* ln1_g   = (const float*)d_in[17];
    const float* ln1_b   = (const float*)d_in[18];
    const float* mlp_W2  = (const float*)d_in[19];
    const float* mlp_b2  = (const float*)d_in[20];
    const float* ln2_g   = (const float*)d_in[21];
    const float* ln2_b   = (const float*)d_in[22];
    const float* Wsrc1   = (const float*)d_in[23];
    const float* bsrc1   = (const float*)d_in[24];
    const float* attn1   = (const float*)d_in[25];
    const float* Wsrc2   = (const float*)d_in[26];
    const float* bsrc2   = (const float*)d_in[27];
    const float* attn2   = (const float*)d_in[28];
    const float* out_W   = (const float*)d_in[29];
    const float* out_b   = (const float*)d_in[30];

    float *hA, *hB, *f, *yA;
    __half *y16, *yA16;
    int *off, *ssrc, *cnt, *cur;
    cudaGetSymbolAddress((void**)&hA,   g_hA);
    cudaGetSymbolAddress((void**)&hB,   g_hB);
    cudaGetSymbolAddress((void**)&f,    g_f);
    cudaGetSymbolAddress((void**)&yA,   g_yA);
    cudaGetSymbolAddress((void**)&y16,  g_y16);
    cudaGetSymbolAddress((void**)&yA16, g_yA16);
    cudaGetSymbolAddress((void**)&off,  g_off);
    cudaGetSymbolAddress((void**)&ssrc, g_ssrc);
    cudaGetSymbolAddress((void**)&cnt,  g_cnt);
    cudaGetSymbolAddress((void**)&cur,  g_cur);

    float* logits = (float*)d_out;
    float* yh_out = (float*)d_out + (size_t)NN * OD;

    // Side stream for the CSR build + y16 conversion (independent of embed+MLP).
    cudaStream_t s2;
    cudaEvent_t ev0, ev1;
    cudaStreamCreateWithFlags(&s2, cudaStreamNonBlocking);
    cudaEventCreateWithFlags(&ev0, cudaEventDisableTiming);
    cudaEventCreateWithFlags(&ev1, cudaEventDisableTiming);

    cudaEventRecord(ev0, 0);

    // ---- main branch: EmbeddingBag + MLP (LN fused) + f-GEMM for prop1 ----
    k_embed<<<(NN + 7) / 8, 256>>>(emb_indices, emb_offsets, emb_weights, embed_W, embed_b, hA);
    dim3 g1((NN + 127) / 128, 1);
    k_gemm<<<g1, 256>>>(hA, mlp_W1, mlp_b1, ln1_g, ln1_b, hB, NN, 128, 1);
    k_gemm<<<g1, 256>>>(hB, mlp_W2, mlp_b2, ln2_g, ln2_b, hA, NN, 128, 1);
    k_gemm<<<g1, 256>>>(hA, Wsrc1, bsrc1, nullptr, nullptr, f, NN, 128, 0);

    // ---- side branch: flag detect + y fp16 conversion + CSR sorts ----
    cudaStreamWaitEvent(s2, ev0, 0);
    k_detect_flag<<<1, 256, 0, s2>>>((const unsigned char*)flag);
    k_y2h<<<(NN * OD / 4 + 255) / 256, 256, 0, s2>>>(y, y16);
    cudaMemsetAsync(cnt, 0, sizeof(int) * 4 * NN, s2);
    dim3 ge((NE + 255) / 256, 4);
    k_hist4<<<ge, 256, 0, s2>>>(dst_p1, dst_s1, dst_p2, dst_s2, cnt);
    k_scan4<<<4, 1024, 0, s2>>>(cnt, off, cur);
    k_scatter4<<<ge, 256, 0, s2>>>(src_p1, dst_p1, src_s1, dst_s1,
                                   src_p2, dst_p2, src_s2, dst_s2, cur, ssrc);
    cudaEventRecord(ev1, s2);

    // ---- join, then props ----
    cudaStreamWaitEvent(0, ev1, 0);
    // prop 1: fp16 label gathers from y16; emits yA (fp32) + yA16 (fp16)
    k_prop<1><<<(NN + 7) / 8, 256>>>(f, hA, y, y16, attn1,
                                     off + 0 * (NN + 1), ssrc + 0 * NE,
                                     off + 1 * (NN + 1), ssrc + 1 * NE,
                                     flag, hB, yA, yA16);

    k_gemm<<<g1, 256>>>(hB, Wsrc2, bsrc2, nullptr, nullptr, f, NN, 128, 0);
    // prop 2: fp16 label gathers from yA16; flagged-copy reads exact fp32 yA
    k_prop<0><<<(NN + 7) / 8, 256>>>(f, hB, yA, yA16, attn2,
                                     off + 2 * (NN + 1), ssrc + 2 * NE,
                                     off + 3 * (NN + 1), ssrc + 3 * NE,
                                     flag, hA, yh_out, nullptr);

    // ---- logits = h @ out_W + out_b ----
    dim3 g2((NN + 127) / 128, 2);
    k_gemm<<<g2, 256>>>(hA, out_W, out_b, nullptr, nullptr, logits, NN, 256, 0);
}